// round 1
// baseline (speedup 1.0000x reference)
#include <cuda_runtime.h>
#include <cuda_bf16.h>
#include <math.h>

#define NN 100000
#define EE 1600000
#define ET (EE + NN)
#define F_IN 500
#define HID 16
#define HEADS 8
#define F1 (HEADS * HID)   // 128
#define NCLS 10

// ---------------- scratch (static device globals; no runtime allocation) ----
__device__ float    g_bufA[(size_t)NN * F1];    // gemm output / h features
__device__ float    g_bufB[(size_t)NN * F1];    // aggregation target / next input
__device__ float    g_als[(size_t)NN * HEADS];
__device__ float    g_ald[(size_t)NN * HEADS];
__device__ unsigned g_m[(size_t)NN * HEADS];
__device__ float    g_denom[(size_t)NN * HEADS];
__device__ float    g_p[(size_t)ET * HEADS];    // edge logits -> probs

// ---------------- helpers ---------------------------------------------------
__device__ __forceinline__ unsigned encf(float f) {
    unsigned u = __float_as_uint(f);
    return (u & 0x80000000u) ? ~u : (u | 0x80000000u);
}
__device__ __forceinline__ float decf(unsigned u) {
    return (u & 0x80000000u) ? __uint_as_float(u & 0x7fffffffu)
                             : __uint_as_float(~u);
}

__global__ void fill_f(float* p, float v, int n) {
    int i = blockIdx.x * blockDim.x + threadIdx.x;
    if (i < n) p[i] = v;
}
__global__ void fill_u(unsigned* p, unsigned v, int n) {
    int i = blockIdx.x * blockDim.x + threadIdx.x;
    if (i < n) p[i] = v;
}

// ---------------- SGEMM: C[M,N] = A[M,K] @ B[K,N] ---------------------------
#define BM 64
#define BN 64
#define BK 16
__global__ __launch_bounds__(256) void sgemm(const float* __restrict__ A,
                                             const float* __restrict__ B,
                                             float* __restrict__ C,
                                             int M, int N, int K) {
    __shared__ float As[BM][BK + 1];
    __shared__ float Bs[BK][BN];
    int tid = threadIdx.x;
    int row0 = blockIdx.y * BM, col0 = blockIdx.x * BN;
    int ty = tid / 16, tx = tid % 16;
    float acc[4][4];
#pragma unroll
    for (int i = 0; i < 4; i++)
#pragma unroll
        for (int j = 0; j < 4; j++) acc[i][j] = 0.f;

    for (int k0 = 0; k0 < K; k0 += BK) {
#pragma unroll
        for (int i = 0; i < 4; i++) {
            int lin = tid + i * 256;          // over BM*BK
            int k = lin % BK, m = lin / BK;   // coalesced along K
            int gr = row0 + m, gk = k0 + k;
            As[m][k] = (gr < M && gk < K) ? A[(long)gr * K + gk] : 0.f;
        }
#pragma unroll
        for (int i = 0; i < 4; i++) {
            int lin = tid + i * 256;          // over BK*BN
            int n = lin % BN, k = lin / BN;   // coalesced along N
            int gk = k0 + k, gc = col0 + n;
            Bs[k][n] = (gk < K && gc < N) ? B[(long)gk * N + gc] : 0.f;
        }
        __syncthreads();
#pragma unroll
        for (int k = 0; k < BK; k++) {
            float ra[4], rb[4];
#pragma unroll
            for (int j = 0; j < 4; j++) {
                ra[j] = As[ty * 4 + j][k];
                rb[j] = Bs[k][tx * 4 + j];
            }
#pragma unroll
            for (int i = 0; i < 4; i++)
#pragma unroll
                for (int j = 0; j < 4; j++) acc[i][j] += ra[i] * rb[j];
        }
        __syncthreads();
    }
#pragma unroll
    for (int i = 0; i < 4; i++) {
        int gr = row0 + ty * 4 + i;
        if (gr >= M) continue;
#pragma unroll
        for (int j = 0; j < 4; j++) {
            int gc = col0 + tx * 4 + j;
            if (gc < N) C[(long)gr * N + gc] = acc[i][j];
        }
    }
}

// ---------------- per-node attention coefficients ---------------------------
__global__ void node_alpha(const float* __restrict__ h,
                           const float* __restrict__ a_src,
                           const float* __restrict__ a_dst,
                           float* __restrict__ als, float* __restrict__ ald,
                           int n_nodes, int H, int C) {
    int idx = blockIdx.x * blockDim.x + threadIdx.x;
    if (idx >= n_nodes * H) return;
    int hh = idx % H, n = idx / H;
    const float* row = h + (long)n * H * C + hh * C;
    float s = 0.f, d = 0.f;
    for (int c = 0; c < C; c++) {
        float v = row[c];
        s += v * a_src[hh * C + c];
        d += v * a_dst[hh * C + c];
    }
    als[idx] = s;
    ald[idx] = d;
}

// ---------------- edge pass A: logits + segment max -------------------------
__global__ void edge_logits(const int* __restrict__ ei,
                            const float* __restrict__ als,
                            const float* __restrict__ ald,
                            float* __restrict__ p, unsigned* __restrict__ m,
                            int E, int Etot, int H) {
    int idx = blockIdx.x * blockDim.x + threadIdx.x;
    if (idx >= Etot * H) return;
    int h = idx % H, e = idx / H;
    int src, dst;
    if (e < E) { src = ei[e]; dst = ei[E + e]; }
    else       { src = dst = e - E; }
    float v = als[src * H + h] + ald[dst * H + h];
    v = v > 0.f ? v : 0.2f * v;      // LeakyReLU
    p[idx] = v;
    atomicMax(&m[dst * H + h], encf(v));
}

// ---------------- edge pass B: exp + segment sum ----------------------------
__global__ void edge_exp(const int* __restrict__ ei,
                         float* __restrict__ p,
                         const unsigned* __restrict__ m,
                         float* __restrict__ denom,
                         int E, int Etot, int H) {
    int idx = blockIdx.x * blockDim.x + threadIdx.x;
    if (idx >= Etot * H) return;
    int h = idx % H, e = idx / H;
    int dst = (e < E) ? ei[E + e] : e - E;
    float v = expf(p[idx] - decf(m[dst * H + h]));
    p[idx] = v;
    atomicAdd(&denom[dst * H + h], v);
}

// ---------------- edge pass C: weighted scatter-add -------------------------
__global__ void edge_aggregate(const int* __restrict__ ei,
                               const float* __restrict__ p,
                               const float* __restrict__ denom,
                               const float* __restrict__ hfeat,
                               float* __restrict__ out,
                               int E, int Etot, int H, int C) {
    int e = blockIdx.x;
    int t = threadIdx.x;
    int F = H * C;
    if (e >= Etot || t >= F) return;
    int src, dst;
    if (e < E) { src = ei[e]; dst = ei[E + e]; }
    else       { src = dst = e - E; }
    int h = t / C;
    float d = denom[dst * H + h];
    float alpha = p[e * H + h] / fmaxf(d, 1e-16f);
    atomicAdd(&out[(long)dst * F + t], hfeat[(long)src * F + t] * alpha);
}

// ---------------- bias + ELU + eval BN (in place) ---------------------------
__global__ void post_bn_elu(float* __restrict__ buf,
                            const float* __restrict__ b,
                            const float* __restrict__ g,
                            const float* __restrict__ be,
                            int n_nodes, int F) {
    int idx = blockIdx.x * blockDim.x + threadIdx.x;
    if (idx >= n_nodes * F) return;
    int c = idx % F;
    float v = buf[idx] + b[c];
    v = v > 0.f ? v : expm1f(v);                 // ELU
    float scale = g[c] * rsqrtf(1.0f + 1e-5f);   // BN eval, mean 0 var 1
    buf[idx] = v * scale + be[c];
}

// ---------------- final: bias + log_softmax (in place on d_out) -------------
__global__ void final_lsm(float* __restrict__ out, const float* __restrict__ b,
                          int n_nodes, int C) {
    int n = blockIdx.x * blockDim.x + threadIdx.x;
    if (n >= n_nodes) return;
    float v[NCLS];
    float mx = -INFINITY;
    for (int c = 0; c < C; c++) {
        v[c] = out[(long)n * C + c] + b[c];
        mx = fmaxf(mx, v[c]);
    }
    float s = 0.f;
    for (int c = 0; c < C; c++) s += expf(v[c] - mx);
    float l = mx + logf(s);
    for (int c = 0; c < C; c++) out[(long)n * C + c] = v[c] - l;
}

// ---------------- driver -----------------------------------------------------
static inline int cdiv(int a, int b) { return (a + b - 1) / b; }

extern "C" void kernel_launch(void* const* d_in, const int* in_sizes, int n_in,
                              void* d_out, int out_size) {
    const float* x    = (const float*)d_in[0];
    const int*   ei   = (const int*)d_in[1];
    const float* W1   = (const float*)d_in[2];
    const float* a1s  = (const float*)d_in[3];
    const float* a1d  = (const float*)d_in[4];
    const float* b1   = (const float*)d_in[5];
    const float* g1   = (const float*)d_in[6];
    const float* be1  = (const float*)d_in[7];
    const float* W2   = (const float*)d_in[8];
    const float* a2s  = (const float*)d_in[9];
    const float* a2d  = (const float*)d_in[10];
    const float* b2   = (const float*)d_in[11];
    const float* g2   = (const float*)d_in[12];
    const float* be2  = (const float*)d_in[13];
    const float* W3   = (const float*)d_in[14];
    const float* a3s  = (const float*)d_in[15];
    const float* a3d  = (const float*)d_in[16];
    const float* b3   = (const float*)d_in[17];
    float* out = (float*)d_out;

    float *bufA, *bufB, *als, *ald, *denom, *pbuf;
    unsigned* mbuf;
    cudaGetSymbolAddress((void**)&bufA, g_bufA);
    cudaGetSymbolAddress((void**)&bufB, g_bufB);
    cudaGetSymbolAddress((void**)&als, g_als);
    cudaGetSymbolAddress((void**)&ald, g_ald);
    cudaGetSymbolAddress((void**)&mbuf, g_m);
    cudaGetSymbolAddress((void**)&denom, g_denom);
    cudaGetSymbolAddress((void**)&pbuf, g_p);

    const int TB = 256;
    const int NH = NN * HEADS;
    const int EH = ET * HEADS;

    // ================= conv1: x[N,500] @ W1 -> bufA[N,128] ==================
    {
        dim3 grid(cdiv(F1, BN), cdiv(NN, BM));
        sgemm<<<grid, 256>>>(x, W1, bufA, NN, F1, F_IN);
    }
    node_alpha<<<cdiv(NH, TB), TB>>>(bufA, a1s, a1d, als, ald, NN, HEADS, HID);
    fill_u<<<cdiv(NH, TB), TB>>>(mbuf, 0u, NH);
    fill_f<<<cdiv(NH, TB), TB>>>(denom, 0.f, NH);
    fill_f<<<cdiv(NN * F1, TB), TB>>>(bufB, 0.f, NN * F1);
    edge_logits<<<cdiv(EH, TB), TB>>>(ei, als, ald, pbuf, mbuf, EE, ET, HEADS);
    edge_exp<<<cdiv(EH, TB), TB>>>(ei, pbuf, mbuf, denom, EE, ET, HEADS);
    edge_aggregate<<<ET, F1>>>(ei, pbuf, denom, bufA, bufB, EE, ET, HEADS, HID);
    post_bn_elu<<<cdiv(NN * F1, TB), TB>>>(bufB, b1, g1, be1, NN, F1);

    // ================= conv2: bufB[N,128] @ W2 -> bufA ======================
    {
        dim3 grid(cdiv(F1, BN), cdiv(NN, BM));
        sgemm<<<grid, 256>>>(bufB, W2, bufA, NN, F1, F1);
    }
    node_alpha<<<cdiv(NH, TB), TB>>>(bufA, a2s, a2d, als, ald, NN, HEADS, HID);
    fill_u<<<cdiv(NH, TB), TB>>>(mbuf, 0u, NH);
    fill_f<<<cdiv(NH, TB), TB>>>(denom, 0.f, NH);
    fill_f<<<cdiv(NN * F1, TB), TB>>>(bufB, 0.f, NN * F1);
    edge_logits<<<cdiv(EH, TB), TB>>>(ei, als, ald, pbuf, mbuf, EE, ET, HEADS);
    edge_exp<<<cdiv(EH, TB), TB>>>(ei, pbuf, mbuf, denom, EE, ET, HEADS);
    edge_aggregate<<<ET, F1>>>(ei, pbuf, denom, bufA, bufB, EE, ET, HEADS, HID);
    post_bn_elu<<<cdiv(NN * F1, TB), TB>>>(bufB, b2, g2, be2, NN, F1);

    // ================= conv3: bufB[N,128] @ W3 -> bufA[N,10] ================
    {
        dim3 grid(cdiv(NCLS, BN), cdiv(NN, BM));
        sgemm<<<grid, 256>>>(bufB, W3, bufA, NN, NCLS, F1);
    }
    node_alpha<<<cdiv(NN, TB), TB>>>(bufA, a3s, a3d, als, ald, NN, 1, NCLS);
    fill_u<<<cdiv(NN, TB), TB>>>(mbuf, 0u, NN);
    fill_f<<<cdiv(NN, TB), TB>>>(denom, 0.f, NN);
    fill_f<<<cdiv(NN * NCLS, TB), TB>>>(out, 0.f, NN * NCLS);
    edge_logits<<<cdiv(ET, TB), TB>>>(ei, als, ald, pbuf, mbuf, EE, ET, 1);
    edge_exp<<<cdiv(ET, TB), TB>>>(ei, pbuf, mbuf, denom, EE, ET, 1);
    edge_aggregate<<<ET, 32>>>(ei, pbuf, denom, bufA, out, EE, ET, 1, NCLS);
    final_lsm<<<cdiv(NN, TB), TB>>>(out, b3, NN, NCLS);
}

// round 2
// speedup vs baseline: 2.8956x; 2.8956x over previous
#include <cuda_runtime.h>
#include <cuda_bf16.h>
#include <math.h>

#define NN 100000
#define EE 1600000
#define ET (EE + NN)
#define F_IN 500
#define HID 16
#define HEADS 8
#define F1 (HEADS * HID)   // 128
#define NCLS 10

// ---------------- scratch (static device globals; no runtime allocation) ----
__device__ float g_bufA[(size_t)NN * F1];
__device__ float g_bufB[(size_t)NN * F1];
__device__ float g_als[(size_t)NN * HEADS];
__device__ float g_ald[(size_t)NN * HEADS];
__device__ float g_denom[(size_t)NN * HEADS];
__device__ float g_p[(size_t)ET * HEADS];
__device__ int   g_deg[NN];
__device__ int   g_rowptr[NN];
__device__ int   g_cursor[NN];
__device__ int   g_bsum[256];
__device__ int   g_boff[256];
__device__ int2  g_csr[(size_t)ET];          // {src, eid}

static inline int cdiv(int a, int b) { return (a + b - 1) / b; }

// ---------------- tiny utils -------------------------------------------------
__global__ void fill_f(float* p, float v, int n) {
    int i = blockIdx.x * blockDim.x + threadIdx.x;
    if (i < n) p[i] = v;
}
__global__ void fill_i(int* p, int v, int n) {
    int i = blockIdx.x * blockDim.x + threadIdx.x;
    if (i < n) p[i] = v;
}

// ---------------- CSR build --------------------------------------------------
__global__ void hist_dst(const int* __restrict__ ei, int* __restrict__ deg) {
    int e = blockIdx.x * blockDim.x + threadIdx.x;
    if (e >= ET) return;
    int dst = (e < EE) ? ei[EE + e] : (e - EE);
    atomicAdd(&deg[dst], 1);
}

#define SCAN_ELEMS 512
// per-block sums
__global__ void scan_s1(const int* __restrict__ deg, int* __restrict__ bsum) {
    __shared__ int sm[256];
    int base = blockIdx.x * SCAN_ELEMS;
    int t = threadIdx.x;
    int i0 = base + 2 * t, i1 = base + 2 * t + 1;
    int v = 0;
    if (i0 < NN) v += deg[i0];
    if (i1 < NN) v += deg[i1];
    sm[t] = v;
    __syncthreads();
    for (int off = 128; off > 0; off >>= 1) {
        if (t < off) sm[t] += sm[t + off];
        __syncthreads();
    }
    if (t == 0) bsum[blockIdx.x] = sm[0];
}
// exclusive scan of block sums (single block)
__global__ void scan_s2(const int* __restrict__ bsum, int* __restrict__ boff, int nb) {
    __shared__ int sm[256];
    int t = threadIdx.x;
    int v = (t < nb) ? bsum[t] : 0;
    sm[t] = v;
    __syncthreads();
    for (int off = 1; off < 256; off <<= 1) {
        int add = (t >= off) ? sm[t - off] : 0;
        __syncthreads();
        sm[t] += add;
        __syncthreads();
    }
    if (t < nb) boff[t] = sm[t] - v;   // exclusive
}
// final: exclusive scan within block + offset; writes rowptr AND cursor
__global__ void scan_s3(const int* __restrict__ deg, const int* __restrict__ boff,
                        int* __restrict__ rowptr, int* __restrict__ cursor) {
    __shared__ int sm[256];
    int base = blockIdx.x * SCAN_ELEMS;
    int t = threadIdx.x;
    int i0 = base + 2 * t, i1 = base + 2 * t + 1;
    int v0 = (i0 < NN) ? deg[i0] : 0;
    int v1 = (i1 < NN) ? deg[i1] : 0;
    int s = v0 + v1;
    sm[t] = s;
    __syncthreads();
    for (int off = 1; off < 256; off <<= 1) {
        int add = (t >= off) ? sm[t - off] : 0;
        __syncthreads();
        sm[t] += add;
        __syncthreads();
    }
    int ex = sm[t] - s + boff[blockIdx.x];
    if (i0 < NN) { rowptr[i0] = ex;      cursor[i0] = ex; }
    if (i1 < NN) { rowptr[i1] = ex + v0; cursor[i1] = ex + v0; }
}

__global__ void csr_scatter(const int* __restrict__ ei, int* __restrict__ cursor,
                            int2* __restrict__ csr) {
    int e = blockIdx.x * blockDim.x + threadIdx.x;
    if (e >= ET) return;
    int src, dst;
    if (e < EE) { src = ei[e]; dst = ei[EE + e]; }
    else        { src = dst = e - EE; }
    int pos = atomicAdd(&cursor[dst], 1);
    csr[pos] = make_int2(src, e);
}

// ---------------- SGEMM: C[M,128] = A[M,K] @ B[K,128] ------------------------
#define GM 128
#define GN 128
#define GK 8
__global__ __launch_bounds__(256, 2) void sgemm128(const float* __restrict__ A,
                                                   const float* __restrict__ B,
                                                   float* __restrict__ C,
                                                   int M, int K) {
    __shared__ float As[GK][GM];
    __shared__ float Bs[GK][GN];
    int tid = threadIdx.x;
    int row0 = blockIdx.x * GM;
    int ty = tid / 16, tx = tid % 16;
    float acc[8][8];
#pragma unroll
    for (int i = 0; i < 8; i++)
#pragma unroll
        for (int j = 0; j < 8; j++) acc[i][j] = 0.f;

    int aRow = tid >> 1;
    int aK   = (tid & 1) * 4;
    int bRow = tid >> 5;
    int bCol = (tid & 31) * 4;
    const float* Aptr = A + (size_t)(row0 + aRow) * K;
    bool aRowOK = (row0 + aRow) < M;

    for (int k0 = 0; k0 < K; k0 += GK) {
        float4 av = make_float4(0.f, 0.f, 0.f, 0.f);
        if (aRowOK) {
            int kk = k0 + aK;
            if (kk + 3 < K) {
                av = *(const float4*)(Aptr + kk);
            } else {
                float tmp[4] = {0.f, 0.f, 0.f, 0.f};
                for (int q = 0; q < 4; q++) if (kk + q < K) tmp[q] = Aptr[kk + q];
                av = make_float4(tmp[0], tmp[1], tmp[2], tmp[3]);
            }
        }
        As[aK + 0][aRow] = av.x;
        As[aK + 1][aRow] = av.y;
        As[aK + 2][aRow] = av.z;
        As[aK + 3][aRow] = av.w;

        float4 bv = make_float4(0.f, 0.f, 0.f, 0.f);
        if (k0 + bRow < K) bv = *(const float4*)(B + (size_t)(k0 + bRow) * GN + bCol);
        *(float4*)&Bs[bRow][bCol] = bv;
        __syncthreads();

#pragma unroll
        for (int kk = 0; kk < GK; kk++) {
            float a[8], b[8];
            *(float4*)(a)     = *(const float4*)&As[kk][ty * 8];
            *(float4*)(a + 4) = *(const float4*)&As[kk][ty * 8 + 4];
            *(float4*)(b)     = *(const float4*)&Bs[kk][tx * 8];
            *(float4*)(b + 4) = *(const float4*)&Bs[kk][tx * 8 + 4];
#pragma unroll
            for (int i = 0; i < 8; i++)
#pragma unroll
                for (int j = 0; j < 8; j++) acc[i][j] = fmaf(a[i], b[j], acc[i][j]);
        }
        __syncthreads();
    }
#pragma unroll
    for (int i = 0; i < 8; i++) {
        int gr = row0 + ty * 8 + i;
        if (gr >= M) continue;
        float4* cp = (float4*)(C + (size_t)gr * GN + tx * 8);
        cp[0] = make_float4(acc[i][0], acc[i][1], acc[i][2], acc[i][3]);
        cp[1] = make_float4(acc[i][4], acc[i][5], acc[i][6], acc[i][7]);
    }
}

// ---------------- small GEMM: C[N,10] = A[N,128] @ W[128,10] -----------------
__global__ void gemm_small(const float* __restrict__ A, const float* __restrict__ W,
                           float* __restrict__ C) {
    __shared__ float Ws[F1 * NCLS];
    for (int i = threadIdx.x; i < F1 * NCLS; i += blockDim.x) Ws[i] = W[i];
    __syncthreads();
    int warp = (blockIdx.x * blockDim.x + threadIdx.x) >> 5;
    int lane = threadIdx.x & 31;
    if (warp >= NN) return;
    float acc[NCLS];
#pragma unroll
    for (int c = 0; c < NCLS; c++) acc[c] = 0.f;
    const float* arow = A + (size_t)warp * F1;
#pragma unroll
    for (int q = 0; q < 4; q++) {
        int k = lane + q * 32;
        float a = arow[k];
#pragma unroll
        for (int c = 0; c < NCLS; c++) acc[c] += a * Ws[k * NCLS + c];
    }
#pragma unroll
    for (int off = 16; off > 0; off >>= 1)
#pragma unroll
        for (int c = 0; c < NCLS; c++) acc[c] += __shfl_xor_sync(0xffffffffu, acc[c], off);
    if (lane < NCLS) C[(size_t)warp * NCLS + lane] = acc[lane];
}

// ---------------- per-node attention coefficients ----------------------------
__global__ void node_alpha(const float* __restrict__ h,
                           const float* __restrict__ a_src,
                           const float* __restrict__ a_dst,
                           float* __restrict__ als, float* __restrict__ ald,
                           int n_nodes, int H, int C) {
    int idx = blockIdx.x * blockDim.x + threadIdx.x;
    if (idx >= n_nodes * H) return;
    int hh = idx % H, n = idx / H;
    const float* row = h + (size_t)n * H * C + hh * C;
    float s = 0.f, d = 0.f;
    for (int c = 0; c < C; c++) {
        float v = row[c];
        s += v * a_src[hh * C + c];
        d += v * a_dst[hh * C + c];
    }
    als[idx] = s;
    ald[idx] = d;
}

// ---------------- fused edge pass: leaky -> exp -> denom (H=8) ---------------
__global__ void edge_p8(const int* __restrict__ ei,
                        const float* __restrict__ als,
                        const float* __restrict__ ald,
                        float* __restrict__ p, float* __restrict__ denom) {
    int e = blockIdx.x * blockDim.x + threadIdx.x;
    if (e >= ET) return;
    int src, dst;
    if (e < EE) { src = ei[e]; dst = ei[EE + e]; }
    else        { src = dst = e - EE; }
    const float4* as4 = (const float4*)(als + (size_t)src * 8);
    const float4* ad4 = (const float4*)(ald + (size_t)dst * 8);
    float4 s0 = as4[0], s1 = as4[1];
    float4 d0 = ad4[0], d1 = ad4[1];
    float v[8];
    v[0] = s0.x + d0.x; v[1] = s0.y + d0.y; v[2] = s0.z + d0.z; v[3] = s0.w + d0.w;
    v[4] = s1.x + d1.x; v[5] = s1.y + d1.y; v[6] = s1.z + d1.z; v[7] = s1.w + d1.w;
#pragma unroll
    for (int h = 0; h < 8; h++) {
        float t = v[h];
        t = t > 0.f ? t : 0.2f * t;
        v[h] = __expf(t);
    }
    float4* p4 = (float4*)(p + (size_t)e * 8);
    p4[0] = make_float4(v[0], v[1], v[2], v[3]);
    p4[1] = make_float4(v[4], v[5], v[6], v[7]);
    float* dn = denom + (size_t)dst * 8;
#pragma unroll
    for (int h = 0; h < 8; h++) atomicAdd(&dn[h], v[h]);
}

// H=1 version (layer 3)
__global__ void edge_p1(const int* __restrict__ ei,
                        const float* __restrict__ als,
                        const float* __restrict__ ald,
                        float* __restrict__ p, float* __restrict__ denom) {
    int e = blockIdx.x * blockDim.x + threadIdx.x;
    if (e >= ET) return;
    int src, dst;
    if (e < EE) { src = ei[e]; dst = ei[EE + e]; }
    else        { src = dst = e - EE; }
    float t = als[src] + ald[dst];
    t = t > 0.f ? t : 0.2f * t;
    float v = __expf(t);
    p[e] = v;
    atomicAdd(&denom[dst], v);
}

// ---------------- gather aggregation + bias + ELU + BN (layers 1,2) ----------
__global__ __launch_bounds__(128) void aggregate128(
    const int2* __restrict__ csr, const int* __restrict__ rowptr,
    const int* __restrict__ deg, const float* __restrict__ p,
    const float* __restrict__ denom, const float* __restrict__ hfeat,
    const float* __restrict__ bias, const float* __restrict__ gamma,
    const float* __restrict__ beta, float* __restrict__ out) {
    int n = blockIdx.x;
    int t = threadIdx.x;
    int start = rowptr[n];
    int len = deg[n];
    int h = t >> 4;
    float invd = 1.f / fmaxf(denom[(size_t)n * 8 + h], 1e-16f);
    float acc = 0.f;
    int src = 0, eid = 0;
    if (len > 0) { int2 c = csr[start]; src = c.x; eid = c.y; }
    for (int i = 0; i < len; i++) {
        int nsrc = src, neid = eid;
        if (i + 1 < len) { int2 c = csr[start + i + 1]; nsrc = c.x; neid = c.y; }
        float alpha = __ldg(&p[(size_t)eid * 8 + h]) * invd;
        acc = fmaf(__ldg(&hfeat[(size_t)src * F1 + t]), alpha, acc);
        src = nsrc; eid = neid;
    }
    float v = acc + bias[t];
    v = v > 0.f ? v : (__expf(v) - 1.f);                 // ELU
    float scale = gamma[t] * rsqrtf(1.0f + 1e-5f);       // eval BN
    out[(size_t)n * F1 + t] = v * scale + beta[t];
}

// layer-3 aggregation: warp per node, 10 classes, raw sums
__global__ __launch_bounds__(128) void aggregate10(
    const int2* __restrict__ csr, const int* __restrict__ rowptr,
    const int* __restrict__ deg, const float* __restrict__ p,
    const float* __restrict__ denom, const float* __restrict__ hfeat,
    float* __restrict__ out) {
    int warp = (blockIdx.x * blockDim.x + threadIdx.x) >> 5;
    int lane = threadIdx.x & 31;
    if (warp >= NN) return;
    int n = warp;
    int start = rowptr[n];
    int len = deg[n];
    float invd = 1.f / fmaxf(denom[n], 1e-16f);
    float acc = 0.f;
    for (int i = 0; i < len; i++) {
        int2 c = csr[start + i];
        float alpha = __ldg(&p[c.y]) * invd;
        if (lane < NCLS) acc = fmaf(__ldg(&hfeat[(size_t)c.x * NCLS + lane]), alpha, acc);
    }
    if (lane < NCLS) out[(size_t)n * NCLS + lane] = acc;
}

// ---------------- final: bias + log_softmax (in place) -----------------------
__global__ void final_lsm(float* __restrict__ out, const float* __restrict__ b) {
    int n = blockIdx.x * blockDim.x + threadIdx.x;
    if (n >= NN) return;
    float v[NCLS];
    float mx = -INFINITY;
#pragma unroll
    for (int c = 0; c < NCLS; c++) {
        v[c] = out[(size_t)n * NCLS + c] + b[c];
        mx = fmaxf(mx, v[c]);
    }
    float s = 0.f;
#pragma unroll
    for (int c = 0; c < NCLS; c++) s += expf(v[c] - mx);
    float l = mx + logf(s);
#pragma unroll
    for (int c = 0; c < NCLS; c++) out[(size_t)n * NCLS + c] = v[c] - l;
}

// ---------------- driver -----------------------------------------------------
extern "C" void kernel_launch(void* const* d_in, const int* in_sizes, int n_in,
                              void* d_out, int out_size) {
    const float* x    = (const float*)d_in[0];
    const int*   ei   = (const int*)d_in[1];
    const float* W1   = (const float*)d_in[2];
    const float* a1s  = (const float*)d_in[3];
    const float* a1d  = (const float*)d_in[4];
    const float* b1   = (const float*)d_in[5];
    const float* g1   = (const float*)d_in[6];
    const float* be1  = (const float*)d_in[7];
    const float* W2   = (const float*)d_in[8];
    const float* a2s  = (const float*)d_in[9];
    const float* a2d  = (const float*)d_in[10];
    const float* b2   = (const float*)d_in[11];
    const float* g2   = (const float*)d_in[12];
    const float* be2  = (const float*)d_in[13];
    const float* W3   = (const float*)d_in[14];
    const float* a3s  = (const float*)d_in[15];
    const float* a3d  = (const float*)d_in[16];
    const float* b3   = (const float*)d_in[17];
    float* out = (float*)d_out;

    float *bufA, *bufB, *als, *ald, *denom, *pbuf;
    int *deg, *rowptr, *cursor, *bsum, *boff;
    int2* csr;
    cudaGetSymbolAddress((void**)&bufA, g_bufA);
    cudaGetSymbolAddress((void**)&bufB, g_bufB);
    cudaGetSymbolAddress((void**)&als, g_als);
    cudaGetSymbolAddress((void**)&ald, g_ald);
    cudaGetSymbolAddress((void**)&denom, g_denom);
    cudaGetSymbolAddress((void**)&pbuf, g_p);
    cudaGetSymbolAddress((void**)&deg, g_deg);
    cudaGetSymbolAddress((void**)&rowptr, g_rowptr);
    cudaGetSymbolAddress((void**)&cursor, g_cursor);
    cudaGetSymbolAddress((void**)&bsum, g_bsum);
    cudaGetSymbolAddress((void**)&boff, g_boff);
    cudaGetSymbolAddress((void**)&csr, g_csr);

    const int TB = 256;
    const int NH = NN * HEADS;
    const int NB_SCAN = cdiv(NN, SCAN_ELEMS);   // 196

    // ---- CSR build (by dst), once per launch ----
    fill_i<<<cdiv(NN, TB), TB>>>(deg, 0, NN);
    hist_dst<<<cdiv(ET, TB), TB>>>(ei, deg);
    scan_s1<<<NB_SCAN, 256>>>(deg, bsum);
    scan_s2<<<1, 256>>>(bsum, boff, NB_SCAN);
    scan_s3<<<NB_SCAN, 256>>>(deg, boff, rowptr, cursor);
    csr_scatter<<<cdiv(ET, TB), TB>>>(ei, cursor, csr);

    // ---- layer 1 ----
    sgemm128<<<cdiv(NN, GM), 256>>>(x, W1, bufA, NN, F_IN);
    node_alpha<<<cdiv(NH, TB), TB>>>(bufA, a1s, a1d, als, ald, NN, HEADS, HID);
    fill_f<<<cdiv(NH, TB), TB>>>(denom, 0.f, NH);
    edge_p8<<<cdiv(ET, TB), TB>>>(ei, als, ald, pbuf, denom);
    aggregate128<<<NN, 128>>>(csr, rowptr, deg, pbuf, denom, bufA, b1, g1, be1, bufB);

    // ---- layer 2 ----
    sgemm128<<<cdiv(NN, GM), 256>>>(bufB, W2, bufA, NN, F1);
    node_alpha<<<cdiv(NH, TB), TB>>>(bufA, a2s, a2d, als, ald, NN, HEADS, HID);
    fill_f<<<cdiv(NH, TB), TB>>>(denom, 0.f, NH);
    edge_p8<<<cdiv(ET, TB), TB>>>(ei, als, ald, pbuf, denom);
    aggregate128<<<NN, 128>>>(csr, rowptr, deg, pbuf, denom, bufA, b2, g2, be2, bufB);

    // ---- layer 3 ----
    gemm_small<<<cdiv(NN * 32, TB), TB>>>(bufB, W3, bufA);
    node_alpha<<<cdiv(NN, TB), TB>>>(bufA, a3s, a3d, als, ald, NN, 1, NCLS);
    fill_f<<<cdiv(NN, TB), TB>>>(denom, 0.f, NN);
    edge_p1<<<cdiv(ET, TB), TB>>>(ei, als, ald, pbuf, denom);
    aggregate10<<<cdiv(NN * 32, 128), 128>>>(csr, rowptr, deg, pbuf, denom, bufA, out);
    final_lsm<<<cdiv(NN, TB), TB>>>(out, b3);
}

// round 3
// speedup vs baseline: 3.7668x; 1.3009x over previous
#include <cuda_runtime.h>
#include <cuda_bf16.h>
#include <math.h>
#include <stdint.h>

#define NN 100000
#define EE 1600000
#define ET (EE + NN)
#define F_IN 500
#define HID 16
#define HEADS 8
#define F1 (HEADS * HID)   // 128
#define NCLS 10

// ---------------- scratch (static device globals; no runtime allocation) ----
__device__ float g_bufA[(size_t)NN * F1];
__device__ float g_bufB[(size_t)NN * F1];
__device__ float g_als[(size_t)NN * HEADS];
__device__ float g_ald[(size_t)NN * HEADS];
__device__ float g_denom[(size_t)NN * HEADS];
__device__ float g_p[(size_t)ET * HEADS];
__device__ int   g_deg[NN];
__device__ int   g_rowptr[NN];
__device__ int   g_cursor[NN];
__device__ int   g_bsum[256];
__device__ int   g_boff[256];
__device__ int2  g_csr[(size_t)ET];          // {src, eid}

static inline int cdiv(int a, int b) { return (a + b - 1) / b; }

// ---------------- tiny utils -------------------------------------------------
__global__ void fill_f(float* p, float v, int n) {
    int i = blockIdx.x * blockDim.x + threadIdx.x;
    if (i < n) p[i] = v;
}
__global__ void fill_i(int* p, int v, int n) {
    int i = blockIdx.x * blockDim.x + threadIdx.x;
    if (i < n) p[i] = v;
}

// ---------------- CSR build --------------------------------------------------
__global__ void hist_dst(const int* __restrict__ ei, int* __restrict__ deg) {
    int e = blockIdx.x * blockDim.x + threadIdx.x;
    if (e >= ET) return;
    int dst = (e < EE) ? ei[EE + e] : (e - EE);
    atomicAdd(&deg[dst], 1);
}

#define SCAN_ELEMS 512
__global__ void scan_s1(const int* __restrict__ deg, int* __restrict__ bsum) {
    __shared__ int sm[256];
    int base = blockIdx.x * SCAN_ELEMS;
    int t = threadIdx.x;
    int i0 = base + 2 * t, i1 = base + 2 * t + 1;
    int v = 0;
    if (i0 < NN) v += deg[i0];
    if (i1 < NN) v += deg[i1];
    sm[t] = v;
    __syncthreads();
    for (int off = 128; off > 0; off >>= 1) {
        if (t < off) sm[t] += sm[t + off];
        __syncthreads();
    }
    if (t == 0) bsum[blockIdx.x] = sm[0];
}
__global__ void scan_s2(const int* __restrict__ bsum, int* __restrict__ boff, int nb) {
    __shared__ int sm[256];
    int t = threadIdx.x;
    int v = (t < nb) ? bsum[t] : 0;
    sm[t] = v;
    __syncthreads();
    for (int off = 1; off < 256; off <<= 1) {
        int add = (t >= off) ? sm[t - off] : 0;
        __syncthreads();
        sm[t] += add;
        __syncthreads();
    }
    if (t < nb) boff[t] = sm[t] - v;   // exclusive
}
__global__ void scan_s3(const int* __restrict__ deg, const int* __restrict__ boff,
                        int* __restrict__ rowptr, int* __restrict__ cursor) {
    __shared__ int sm[256];
    int base = blockIdx.x * SCAN_ELEMS;
    int t = threadIdx.x;
    int i0 = base + 2 * t, i1 = base + 2 * t + 1;
    int v0 = (i0 < NN) ? deg[i0] : 0;
    int v1 = (i1 < NN) ? deg[i1] : 0;
    int s = v0 + v1;
    sm[t] = s;
    __syncthreads();
    for (int off = 1; off < 256; off <<= 1) {
        int add = (t >= off) ? sm[t - off] : 0;
        __syncthreads();
        sm[t] += add;
        __syncthreads();
    }
    int ex = sm[t] - s + boff[blockIdx.x];
    if (i0 < NN) { rowptr[i0] = ex;      cursor[i0] = ex; }
    if (i1 < NN) { rowptr[i1] = ex + v0; cursor[i1] = ex + v0; }
}

__global__ void csr_scatter(const int* __restrict__ ei, int* __restrict__ cursor,
                            int2* __restrict__ csr) {
    int e = blockIdx.x * blockDim.x + threadIdx.x;
    if (e >= ET) return;
    int src, dst;
    if (e < EE) { src = ei[e]; dst = ei[EE + e]; }
    else        { src = dst = e - EE; }
    int pos = atomicAdd(&cursor[dst], 1);
    csr[pos] = make_int2(src, e);
}

// ---------------- TF32 tensor-core GEMM: C[M,128] = A[M,K] @ B[K,128] --------
// Block: 256 threads = 8 warps (4x2), block tile 128x128, warp tile 32x64.
// KC=16 k-chunk. Conflict-free smem strides: As stride 20, Bs stride 136.
#define KC 16
#define AS_STR 20
#define BS_STR 136

__device__ __forceinline__ uint32_t f2tf32(float v) {
    uint32_t t;
    asm("cvt.rna.tf32.f32 %0, %1;" : "=r"(t) : "f"(v));
    return t;
}

__global__ __launch_bounds__(256, 2) void gemm_tf32(const float* __restrict__ A,
                                                    const float* __restrict__ B,
                                                    float* __restrict__ C,
                                                    int M, int K) {
    __shared__ uint32_t As[128 * AS_STR];   // [m][k]
    __shared__ uint32_t Bs[KC * BS_STR];    // [k][n]
    int tid = threadIdx.x;
    int wid = tid >> 5, lane = tid & 31;
    int wm = (wid & 3) * 32;     // warp row offset
    int wn = (wid >> 2) * 64;    // warp col offset
    int row0 = blockIdx.x * 128;
    int gid = lane >> 2;         // groupID
    int tk = lane & 3;

    float acc[2][8][4];
#pragma unroll
    for (int mi = 0; mi < 2; mi++)
#pragma unroll
        for (int ni = 0; ni < 8; ni++)
#pragma unroll
            for (int q = 0; q < 4; q++) acc[mi][ni][q] = 0.f;

    for (int k0 = 0; k0 < K; k0 += KC) {
        // A tile 128xKC, scalar loads (K=500 rows not 16B aligned)
#pragma unroll
        for (int i = 0; i < 8; i++) {
            int idx = tid + i * 256;          // 0..2047
            int k = idx & 15, m = idx >> 4;
            float v = 0.f;
            int gr = row0 + m, gk = k0 + k;
            if (gr < M && gk < K) v = __ldg(&A[(size_t)gr * K + gk]);
            As[m * AS_STR + k] = f2tf32(v);
        }
        // B tile KCx128, float4 loads (rows of 128 floats, aligned)
#pragma unroll
        for (int i = 0; i < 2; i++) {
            int idx = tid + i * 256;          // 0..511
            int c4 = idx & 31, k = idx >> 5;
            float4 v = make_float4(0.f, 0.f, 0.f, 0.f);
            if (k0 + k < K) v = *(const float4*)(B + (size_t)(k0 + k) * 128 + c4 * 4);
            uint32_t* bp = &Bs[k * BS_STR + c4 * 4];
            bp[0] = f2tf32(v.x); bp[1] = f2tf32(v.y);
            bp[2] = f2tf32(v.z); bp[3] = f2tf32(v.w);
        }
        __syncthreads();

#pragma unroll
        for (int ks = 0; ks < 2; ks++) {
            int kb = ks * 8;
            uint32_t af[2][4];
#pragma unroll
            for (int mi = 0; mi < 2; mi++) {
                int r = wm + mi * 16 + gid;
                af[mi][0] = As[r * AS_STR + kb + tk];
                af[mi][1] = As[(r + 8) * AS_STR + kb + tk];
                af[mi][2] = As[r * AS_STR + kb + tk + 4];
                af[mi][3] = As[(r + 8) * AS_STR + kb + tk + 4];
            }
            uint32_t bf[8][2];
#pragma unroll
            for (int ni = 0; ni < 8; ni++) {
                int c = wn + ni * 8 + gid;
                bf[ni][0] = Bs[(kb + tk) * BS_STR + c];
                bf[ni][1] = Bs[(kb + tk + 4) * BS_STR + c];
            }
#pragma unroll
            for (int mi = 0; mi < 2; mi++)
#pragma unroll
                for (int ni = 0; ni < 8; ni++) {
                    asm volatile(
                        "mma.sync.aligned.m16n8k8.row.col.f32.tf32.tf32.f32 "
                        "{%0,%1,%2,%3}, {%4,%5,%6,%7}, {%8,%9}, {%0,%1,%2,%3};"
                        : "+f"(acc[mi][ni][0]), "+f"(acc[mi][ni][1]),
                          "+f"(acc[mi][ni][2]), "+f"(acc[mi][ni][3])
                        : "r"(af[mi][0]), "r"(af[mi][1]), "r"(af[mi][2]), "r"(af[mi][3]),
                          "r"(bf[ni][0]), "r"(bf[ni][1]));
                }
        }
        __syncthreads();
    }

    // epilogue: c0,c1 at (row=gid, col=2*tk), c2,c3 at row+8
#pragma unroll
    for (int mi = 0; mi < 2; mi++) {
        int r0 = row0 + wm + mi * 16 + gid;
        int r1 = r0 + 8;
#pragma unroll
        for (int ni = 0; ni < 8; ni++) {
            int c = wn + ni * 8 + tk * 2;
            if (r0 < M) {
                C[(size_t)r0 * 128 + c]     = acc[mi][ni][0];
                C[(size_t)r0 * 128 + c + 1] = acc[mi][ni][1];
            }
            if (r1 < M) {
                C[(size_t)r1 * 128 + c]     = acc[mi][ni][2];
                C[(size_t)r1 * 128 + c + 1] = acc[mi][ni][3];
            }
        }
    }
}

// ---------------- small GEMM: C[N,10] = A[N,128] @ W[128,10] -----------------
__global__ void gemm_small(const float* __restrict__ A, const float* __restrict__ W,
                           float* __restrict__ C) {
    __shared__ float Ws[F1 * NCLS];
    for (int i = threadIdx.x; i < F1 * NCLS; i += blockDim.x) Ws[i] = W[i];
    __syncthreads();
    int warp = (blockIdx.x * blockDim.x + threadIdx.x) >> 5;
    int lane = threadIdx.x & 31;
    if (warp >= NN) return;
    float acc[NCLS];
#pragma unroll
    for (int c = 0; c < NCLS; c++) acc[c] = 0.f;
    const float* arow = A + (size_t)warp * F1;
#pragma unroll
    for (int q = 0; q < 4; q++) {
        int k = lane + q * 32;
        float a = arow[k];
#pragma unroll
        for (int c = 0; c < NCLS; c++) acc[c] += a * Ws[k * NCLS + c];
    }
#pragma unroll
    for (int off = 16; off > 0; off >>= 1)
#pragma unroll
        for (int c = 0; c < NCLS; c++) acc[c] += __shfl_xor_sync(0xffffffffu, acc[c], off);
    if (lane < NCLS) C[(size_t)warp * NCLS + lane] = acc[lane];
}

// ---------------- per-node attention coefficients ----------------------------
__global__ void node_alpha(const float* __restrict__ h,
                           const float* __restrict__ a_src,
                           const float* __restrict__ a_dst,
                           float* __restrict__ als, float* __restrict__ ald,
                           int n_nodes, int H, int C) {
    int idx = blockIdx.x * blockDim.x + threadIdx.x;
    if (idx >= n_nodes * H) return;
    int hh = idx % H, n = idx / H;
    const float* row = h + (size_t)n * H * C + hh * C;
    float s = 0.f, d = 0.f;
    for (int c = 0; c < C; c++) {
        float v = row[c];
        s += v * a_src[hh * C + c];
        d += v * a_dst[hh * C + c];
    }
    als[idx] = s;
    ald[idx] = d;
}

// ---------------- fused edge pass: leaky -> exp -> denom (H=8) ---------------
__global__ void edge_p8(const int* __restrict__ ei,
                        const float* __restrict__ als,
                        const float* __restrict__ ald,
                        float* __restrict__ p, float* __restrict__ denom) {
    int e = blockIdx.x * blockDim.x + threadIdx.x;
    if (e >= ET) return;
    int src, dst;
    if (e < EE) { src = ei[e]; dst = ei[EE + e]; }
    else        { src = dst = e - EE; }
    const float4* as4 = (const float4*)(als + (size_t)src * 8);
    const float4* ad4 = (const float4*)(ald + (size_t)dst * 8);
    float4 s0 = as4[0], s1 = as4[1];
    float4 d0 = ad4[0], d1 = ad4[1];
    float v[8];
    v[0] = s0.x + d0.x; v[1] = s0.y + d0.y; v[2] = s0.z + d0.z; v[3] = s0.w + d0.w;
    v[4] = s1.x + d1.x; v[5] = s1.y + d1.y; v[6] = s1.z + d1.z; v[7] = s1.w + d1.w;
#pragma unroll
    for (int h = 0; h < 8; h++) {
        float t = v[h];
        t = t > 0.f ? t : 0.2f * t;
        v[h] = __expf(t);
    }
    float4* p4 = (float4*)(p + (size_t)e * 8);
    p4[0] = make_float4(v[0], v[1], v[2], v[3]);
    p4[1] = make_float4(v[4], v[5], v[6], v[7]);
    float* dn = denom + (size_t)dst * 8;
#pragma unroll
    for (int h = 0; h < 8; h++) atomicAdd(&dn[h], v[h]);
}

// H=1 version (layer 3)
__global__ void edge_p1(const int* __restrict__ ei,
                        const float* __restrict__ als,
                        const float* __restrict__ ald,
                        float* __restrict__ p, float* __restrict__ denom) {
    int e = blockIdx.x * blockDim.x + threadIdx.x;
    if (e >= ET) return;
    int src, dst;
    if (e < EE) { src = ei[e]; dst = ei[EE + e]; }
    else        { src = dst = e - EE; }
    float t = als[src] + ald[dst];
    t = t > 0.f ? t : 0.2f * t;
    float v = __expf(t);
    p[e] = v;
    atomicAdd(&denom[dst], v);
}

// ---------------- gather aggregation + bias + ELU + BN (layers 1,2) ----------
__global__ __launch_bounds__(128) void aggregate128(
    const int2* __restrict__ csr, const int* __restrict__ rowptr,
    const int* __restrict__ deg, const float* __restrict__ p,
    const float* __restrict__ denom, const float* __restrict__ hfeat,
    const float* __restrict__ bias, const float* __restrict__ gamma,
    const float* __restrict__ beta, float* __restrict__ out) {
    int n = blockIdx.x;
    int t = threadIdx.x;
    int start = rowptr[n];
    int len = deg[n];
    int h = t >> 4;
    float invd = 1.f / fmaxf(denom[(size_t)n * 8 + h], 1e-16f);
    float acc = 0.f;
    int src = 0, eid = 0;
    if (len > 0) { int2 c = csr[start]; src = c.x; eid = c.y; }
    for (int i = 0; i < len; i++) {
        int nsrc = src, neid = eid;
        if (i + 1 < len) { int2 c = csr[start + i + 1]; nsrc = c.x; neid = c.y; }
        float alpha = __ldg(&p[(size_t)eid * 8 + h]) * invd;
        acc = fmaf(__ldg(&hfeat[(size_t)src * F1 + t]), alpha, acc);
        src = nsrc; eid = neid;
    }
    float v = acc + bias[t];
    v = v > 0.f ? v : (__expf(v) - 1.f);                 // ELU
    float scale = gamma[t] * rsqrtf(1.0f + 1e-5f);       // eval BN
    out[(size_t)n * F1 + t] = v * scale + beta[t];
}

// layer-3 aggregation: warp per node, 10 classes, raw sums
__global__ __launch_bounds__(128) void aggregate10(
    const int2* __restrict__ csr, const int* __restrict__ rowptr,
    const int* __restrict__ deg, const float* __restrict__ p,
    const float* __restrict__ denom, const float* __restrict__ hfeat,
    float* __restrict__ out) {
    int warp = (blockIdx.x * blockDim.x + threadIdx.x) >> 5;
    int lane = threadIdx.x & 31;
    if (warp >= NN) return;
    int n = warp;
    int start = rowptr[n];
    int len = deg[n];
    float invd = 1.f / fmaxf(denom[n], 1e-16f);
    float acc = 0.f;
    for (int i = 0; i < len; i++) {
        int2 c = csr[start + i];
        float alpha = __ldg(&p[c.y]) * invd;
        if (lane < NCLS) acc = fmaf(__ldg(&hfeat[(size_t)c.x * NCLS + lane]), alpha, acc);
    }
    if (lane < NCLS) out[(size_t)n * NCLS + lane] = acc;
}

// ---------------- final: bias + log_softmax (in place) -----------------------
__global__ void final_lsm(float* __restrict__ out, const float* __restrict__ b) {
    int n = blockIdx.x * blockDim.x + threadIdx.x;
    if (n >= NN) return;
    float v[NCLS];
    float mx = -INFINITY;
#pragma unroll
    for (int c = 0; c < NCLS; c++) {
        v[c] = out[(size_t)n * NCLS + c] + b[c];
        mx = fmaxf(mx, v[c]);
    }
    float s = 0.f;
#pragma unroll
    for (int c = 0; c < NCLS; c++) s += expf(v[c] - mx);
    float l = mx + logf(s);
#pragma unroll
    for (int c = 0; c < NCLS; c++) out[(size_t)n * NCLS + c] = v[c] - l;
}

// ---------------- driver -----------------------------------------------------
extern "C" void kernel_launch(void* const* d_in, const int* in_sizes, int n_in,
                              void* d_out, int out_size) {
    const float* x    = (const float*)d_in[0];
    const int*   ei   = (const int*)d_in[1];
    const float* W1   = (const float*)d_in[2];
    const float* a1s  = (const float*)d_in[3];
    const float* a1d  = (const float*)d_in[4];
    const float* b1   = (const float*)d_in[5];
    const float* g1   = (const float*)d_in[6];
    const float* be1  = (const float*)d_in[7];
    const float* W2   = (const float*)d_in[8];
    const float* a2s  = (const float*)d_in[9];
    const float* a2d  = (const float*)d_in[10];
    const float* b2   = (const float*)d_in[11];
    const float* g2   = (const float*)d_in[12];
    const float* be2  = (const float*)d_in[13];
    const float* W3   = (const float*)d_in[14];
    const float* a3s  = (const float*)d_in[15];
    const float* a3d  = (const float*)d_in[16];
    const float* b3   = (const float*)d_in[17];
    float* out = (float*)d_out;

    float *bufA, *bufB, *als, *ald, *denom, *pbuf;
    int *deg, *rowptr, *cursor, *bsum, *boff;
    int2* csr;
    cudaGetSymbolAddress((void**)&bufA, g_bufA);
    cudaGetSymbolAddress((void**)&bufB, g_bufB);
    cudaGetSymbolAddress((void**)&als, g_als);
    cudaGetSymbolAddress((void**)&ald, g_ald);
    cudaGetSymbolAddress((void**)&denom, g_denom);
    cudaGetSymbolAddress((void**)&pbuf, g_p);
    cudaGetSymbolAddress((void**)&deg, g_deg);
    cudaGetSymbolAddress((void**)&rowptr, g_rowptr);
    cudaGetSymbolAddress((void**)&cursor, g_cursor);
    cudaGetSymbolAddress((void**)&bsum, g_bsum);
    cudaGetSymbolAddress((void**)&boff, g_boff);
    cudaGetSymbolAddress((void**)&csr, g_csr);

    const int TB = 256;
    const int NH = NN * HEADS;
    const int NB_SCAN = cdiv(NN, SCAN_ELEMS);

    // ---- CSR build (by dst) ----
    fill_i<<<cdiv(NN, TB), TB>>>(deg, 0, NN);
    hist_dst<<<cdiv(ET, TB), TB>>>(ei, deg);
    scan_s1<<<NB_SCAN, 256>>>(deg, bsum);
    scan_s2<<<1, 256>>>(bsum, boff, NB_SCAN);
    scan_s3<<<NB_SCAN, 256>>>(deg, boff, rowptr, cursor);
    csr_scatter<<<cdiv(ET, TB), TB>>>(ei, cursor, csr);

    // ---- layer 1 ----
    gemm_tf32<<<cdiv(NN, 128), 256>>>(x, W1, bufA, NN, F_IN);
    node_alpha<<<cdiv(NH, TB), TB>>>(bufA, a1s, a1d, als, ald, NN, HEADS, HID);
    fill_f<<<cdiv(NH, TB), TB>>>(denom, 0.f, NH);
    edge_p8<<<cdiv(ET, TB), TB>>>(ei, als, ald, pbuf, denom);
    aggregate128<<<NN, 128>>>(csr, rowptr, deg, pbuf, denom, bufA, b1, g1, be1, bufB);

    // ---- layer 2 ----
    gemm_tf32<<<cdiv(NN, 128), 256>>>(bufB, W2, bufA, NN, F1);
    node_alpha<<<cdiv(NH, TB), TB>>>(bufA, a2s, a2d, als, ald, NN, HEADS, HID);
    fill_f<<<cdiv(NH, TB), TB>>>(denom, 0.f, NH);
    edge_p8<<<cdiv(ET, TB), TB>>>(ei, als, ald, pbuf, denom);
    aggregate128<<<NN, 128>>>(csr, rowptr, deg, pbuf, denom, bufA, b2, g2, be2, bufB);

    // ---- layer 3 ----
    gemm_small<<<cdiv(NN * 32, TB), TB>>>(bufB, W3, bufA);
    node_alpha<<<cdiv(NN, TB), TB>>>(bufA, a3s, a3d, als, ald, NN, 1, NCLS);
    fill_f<<<cdiv(NN, TB), TB>>>(denom, 0.f, NN);
    edge_p1<<<cdiv(ET, TB), TB>>>(ei, als, ald, pbuf, denom);
    aggregate10<<<cdiv(NN * 32, 128), 128>>>(csr, rowptr, deg, pbuf, denom, bufA, out);
    final_lsm<<<cdiv(NN, TB), TB>>>(out, b3);
}

// round 4
// speedup vs baseline: 4.7482x; 1.2605x over previous
#include <cuda_runtime.h>
#include <cuda_bf16.h>
#include <math.h>
#include <stdint.h>

#define NN 100000
#define EE 1600000
#define ET (EE + NN)
#define F_IN 500
#define HID 16
#define HEADS 8
#define F1 (HEADS * HID)   // 128
#define NCLS 10

// ---------------- scratch (static device globals) ---------------------------
__device__ float g_bufA[(size_t)NN * F1];
__device__ float g_bufB[(size_t)NN * F1];
__device__ float g_als[(size_t)NN * HEADS];
__device__ float g_ald[(size_t)NN * HEADS];
__device__ int   g_deg[NN];
__device__ int   g_rowptr[NN];
__device__ int   g_cursor[NN];
__device__ int   g_bsum[256];
__device__ int   g_boff[256];
__device__ int   g_csr[(size_t)ET];          // src node per CSR slot

static inline int cdiv(int a, int b) { return (a + b - 1) / b; }

// ---------------- tiny utils -------------------------------------------------
__global__ void fill_i(int* p, int v, int n) {
    int i = blockIdx.x * blockDim.x + threadIdx.x;
    if (i < n) p[i] = v;
}

// ---------------- CSR build --------------------------------------------------
__global__ void hist_dst(const int* __restrict__ ei, int* __restrict__ deg) {
    int e = blockIdx.x * blockDim.x + threadIdx.x;
    if (e >= ET) return;
    int dst = (e < EE) ? ei[EE + e] : (e - EE);
    atomicAdd(&deg[dst], 1);
}

#define SCAN_ELEMS 512
__global__ void scan_s1(const int* __restrict__ deg, int* __restrict__ bsum) {
    __shared__ int sm[256];
    int base = blockIdx.x * SCAN_ELEMS;
    int t = threadIdx.x;
    int i0 = base + 2 * t, i1 = base + 2 * t + 1;
    int v = 0;
    if (i0 < NN) v += deg[i0];
    if (i1 < NN) v += deg[i1];
    sm[t] = v;
    __syncthreads();
    for (int off = 128; off > 0; off >>= 1) {
        if (t < off) sm[t] += sm[t + off];
        __syncthreads();
    }
    if (t == 0) bsum[blockIdx.x] = sm[0];
}
__global__ void scan_s2(const int* __restrict__ bsum, int* __restrict__ boff, int nb) {
    __shared__ int sm[256];
    int t = threadIdx.x;
    int v = (t < nb) ? bsum[t] : 0;
    sm[t] = v;
    __syncthreads();
    for (int off = 1; off < 256; off <<= 1) {
        int add = (t >= off) ? sm[t - off] : 0;
        __syncthreads();
        sm[t] += add;
        __syncthreads();
    }
    if (t < nb) boff[t] = sm[t] - v;   // exclusive
}
__global__ void scan_s3(const int* __restrict__ deg, const int* __restrict__ boff,
                        int* __restrict__ rowptr, int* __restrict__ cursor) {
    __shared__ int sm[256];
    int base = blockIdx.x * SCAN_ELEMS;
    int t = threadIdx.x;
    int i0 = base + 2 * t, i1 = base + 2 * t + 1;
    int v0 = (i0 < NN) ? deg[i0] : 0;
    int v1 = (i1 < NN) ? deg[i1] : 0;
    int s = v0 + v1;
    sm[t] = s;
    __syncthreads();
    for (int off = 1; off < 256; off <<= 1) {
        int add = (t >= off) ? sm[t - off] : 0;
        __syncthreads();
        sm[t] += add;
        __syncthreads();
    }
    int ex = sm[t] - s + boff[blockIdx.x];
    if (i0 < NN) { rowptr[i0] = ex;      cursor[i0] = ex; }
    if (i1 < NN) { rowptr[i1] = ex + v0; cursor[i1] = ex + v0; }
}

__global__ void csr_scatter(const int* __restrict__ ei, int* __restrict__ cursor,
                            int* __restrict__ csr) {
    int e = blockIdx.x * blockDim.x + threadIdx.x;
    if (e >= ET) return;
    int src, dst;
    if (e < EE) { src = ei[e]; dst = ei[EE + e]; }
    else        { src = dst = e - EE; }
    int pos = atomicAdd(&cursor[dst], 1);
    csr[pos] = src;
}

// ---------------- TF32 tensor-core GEMM: C[M,128] = A[M,K] @ B[K,128] --------
#define KC 16
#define AS_STR 20
#define BS_STR 136

__device__ __forceinline__ uint32_t f2tf32(float v) {
    uint32_t t;
    asm("cvt.rna.tf32.f32 %0, %1;" : "=r"(t) : "f"(v));
    return t;
}

__global__ __launch_bounds__(256, 2) void gemm_tf32(const float* __restrict__ A,
                                                    const float* __restrict__ B,
                                                    float* __restrict__ C,
                                                    int M, int K) {
    __shared__ uint32_t As[128 * AS_STR];   // [m][k]
    __shared__ uint32_t Bs[KC * BS_STR];    // [k][n]
    int tid = threadIdx.x;
    int wid = tid >> 5, lane = tid & 31;
    int wm = (wid & 3) * 32;
    int wn = (wid >> 2) * 64;
    int row0 = blockIdx.x * 128;
    int gid = lane >> 2;
    int tk = lane & 3;

    float acc[2][8][4];
#pragma unroll
    for (int mi = 0; mi < 2; mi++)
#pragma unroll
        for (int ni = 0; ni < 8; ni++)
#pragma unroll
            for (int q = 0; q < 4; q++) acc[mi][ni][q] = 0.f;

    // A loader: 512 float4 per chunk -> thread handles 2
    int aIdx0 = tid, aIdx1 = tid + 256;
    int aK0 = (aIdx0 & 3) * 4, aM0 = aIdx0 >> 2;
    int aK1 = (aIdx1 & 3) * 4, aM1 = aIdx1 >> 2;
    bool aOK0 = (row0 + aM0) < M;
    bool aOK1 = (row0 + aM1) < M;
    const float* Ap0 = A + (size_t)(row0 + aM0) * K;
    const float* Ap1 = A + (size_t)(row0 + aM1) * K;

    for (int k0 = 0; k0 < K; k0 += KC) {
        {
            int gk = k0 + aK0;
            float4 v = make_float4(0.f, 0.f, 0.f, 0.f);
            if (aOK0 && gk < K) v = *(const float4*)(Ap0 + gk);   // K%4==0 => safe
            uint32_t* ap = &As[aM0 * AS_STR + aK0];
            ap[0] = f2tf32(v.x); ap[1] = f2tf32(v.y); ap[2] = f2tf32(v.z); ap[3] = f2tf32(v.w);
        }
        {
            int gk = k0 + aK1;
            float4 v = make_float4(0.f, 0.f, 0.f, 0.f);
            if (aOK1 && gk < K) v = *(const float4*)(Ap1 + gk);
            uint32_t* ap = &As[aM1 * AS_STR + aK1];
            ap[0] = f2tf32(v.x); ap[1] = f2tf32(v.y); ap[2] = f2tf32(v.z); ap[3] = f2tf32(v.w);
        }
#pragma unroll
        for (int i = 0; i < 2; i++) {
            int idx = tid + i * 256;
            int c4 = idx & 31, k = idx >> 5;
            float4 v = make_float4(0.f, 0.f, 0.f, 0.f);
            if (k0 + k < K) v = *(const float4*)(B + (size_t)(k0 + k) * 128 + c4 * 4);
            uint32_t* bp = &Bs[k * BS_STR + c4 * 4];
            bp[0] = f2tf32(v.x); bp[1] = f2tf32(v.y); bp[2] = f2tf32(v.z); bp[3] = f2tf32(v.w);
        }
        __syncthreads();

#pragma unroll
        for (int ks = 0; ks < 2; ks++) {
            int kb = ks * 8;
            uint32_t af[2][4];
#pragma unroll
            for (int mi = 0; mi < 2; mi++) {
                int r = wm + mi * 16 + gid;
                af[mi][0] = As[r * AS_STR + kb + tk];
                af[mi][1] = As[(r + 8) * AS_STR + kb + tk];
                af[mi][2] = As[r * AS_STR + kb + tk + 4];
                af[mi][3] = As[(r + 8) * AS_STR + kb + tk + 4];
            }
            uint32_t bf[8][2];
#pragma unroll
            for (int ni = 0; ni < 8; ni++) {
                int c = wn + ni * 8 + gid;
                bf[ni][0] = Bs[(kb + tk) * BS_STR + c];
                bf[ni][1] = Bs[(kb + tk + 4) * BS_STR + c];
            }
#pragma unroll
            for (int mi = 0; mi < 2; mi++)
#pragma unroll
                for (int ni = 0; ni < 8; ni++) {
                    asm volatile(
                        "mma.sync.aligned.m16n8k8.row.col.f32.tf32.tf32.f32 "
                        "{%0,%1,%2,%3}, {%4,%5,%6,%7}, {%8,%9}, {%0,%1,%2,%3};"
                        : "+f"(acc[mi][ni][0]), "+f"(acc[mi][ni][1]),
                          "+f"(acc[mi][ni][2]), "+f"(acc[mi][ni][3])
                        : "r"(af[mi][0]), "r"(af[mi][1]), "r"(af[mi][2]), "r"(af[mi][3]),
                          "r"(bf[ni][0]), "r"(bf[ni][1]));
                }
        }
        __syncthreads();
    }

#pragma unroll
    for (int mi = 0; mi < 2; mi++) {
        int r0 = row0 + wm + mi * 16 + gid;
        int r1 = r0 + 8;
#pragma unroll
        for (int ni = 0; ni < 8; ni++) {
            int c = wn + ni * 8 + tk * 2;
            if (r0 < M) {
                C[(size_t)r0 * 128 + c]     = acc[mi][ni][0];
                C[(size_t)r0 * 128 + c + 1] = acc[mi][ni][1];
            }
            if (r1 < M) {
                C[(size_t)r1 * 128 + c]     = acc[mi][ni][2];
                C[(size_t)r1 * 128 + c + 1] = acc[mi][ni][3];
            }
        }
    }
}

// ---------------- node alphas, warp per node (layers 1,2) --------------------
__global__ __launch_bounds__(256) void node_alpha_w(const float* __restrict__ h,
                                                    const float* __restrict__ a_src,
                                                    const float* __restrict__ a_dst,
                                                    float* __restrict__ als,
                                                    float* __restrict__ ald) {
    __shared__ float s_as[F1], s_ad[F1];
    int t = threadIdx.x;
    if (t < F1) { s_as[t] = a_src[t]; s_ad[t] = a_dst[t]; }
    __syncthreads();
    int warp = (blockIdx.x * blockDim.x + t) >> 5;
    int lane = t & 31;
    if (warp >= NN) return;
    int c0 = lane * 4;
    float4 v = *(const float4*)(h + (size_t)warp * F1 + c0);
    float s = v.x * s_as[c0] + v.y * s_as[c0 + 1] + v.z * s_as[c0 + 2] + v.w * s_as[c0 + 3];
    float d = v.x * s_ad[c0] + v.y * s_ad[c0 + 1] + v.z * s_ad[c0 + 2] + v.w * s_ad[c0 + 3];
    s += __shfl_xor_sync(0xffffffffu, s, 1);
    s += __shfl_xor_sync(0xffffffffu, s, 2);
    d += __shfl_xor_sync(0xffffffffu, d, 1);
    d += __shfl_xor_sync(0xffffffffu, d, 2);
    if ((lane & 3) == 0) {
        int hh = lane >> 2;
        als[(size_t)warp * HEADS + hh] = s;
        ald[(size_t)warp * HEADS + hh] = d;
    }
}

// ---------------- fused aggregation (layers 1,2) -----------------------------
// block = 128 threads = one dst node; p computed on the fly; denom deferred.
__global__ __launch_bounds__(128) void aggregate_fused(
    const int* __restrict__ csr, const int* __restrict__ rowptr,
    const int* __restrict__ deg, const float* __restrict__ als,
    const float* __restrict__ ald, const float* __restrict__ hfeat,
    const float* __restrict__ bias, const float* __restrict__ gamma,
    const float* __restrict__ beta, float* __restrict__ out) {
    int n = blockIdx.x;
    int t = threadIdx.x;
    int lane = t & 31;
    int start = rowptr[n];
    int len = deg[n];
    int h = t >> 4;
    bool leader = (lane & 15) == 0;
    float myald = leader ? __ldg(&ald[(size_t)n * HEADS + h]) : 0.f;

    float acc = 0.f, dsum = 0.f;
    int i = 0;
    for (; i + 2 <= len; i += 2) {
        int s0 = __ldg(&csr[start + i]);
        int s1 = __ldg(&csr[start + i + 1]);
        float f0 = __ldg(&hfeat[(size_t)s0 * F1 + t]);
        float f1 = __ldg(&hfeat[(size_t)s1 * F1 + t]);
        float p0 = 0.f, p1 = 0.f;
        if (leader) {
            float l0 = __ldg(&als[(size_t)s0 * HEADS + h]) + myald;
            float l1 = __ldg(&als[(size_t)s1 * HEADS + h]) + myald;
            l0 = l0 > 0.f ? l0 : 0.2f * l0;
            l1 = l1 > 0.f ? l1 : 0.2f * l1;
            p0 = __expf(l0);
            p1 = __expf(l1);
        }
        p0 = __shfl_sync(0xffffffffu, p0, lane & 16);
        p1 = __shfl_sync(0xffffffffu, p1, lane & 16);
        dsum += p0 + p1;
        acc = fmaf(p0, f0, fmaf(p1, f1, acc));
    }
    if (i < len) {
        int s0 = __ldg(&csr[start + i]);
        float f0 = __ldg(&hfeat[(size_t)s0 * F1 + t]);
        float p0 = 0.f;
        if (leader) {
            float l0 = __ldg(&als[(size_t)s0 * HEADS + h]) + myald;
            l0 = l0 > 0.f ? l0 : 0.2f * l0;
            p0 = __expf(l0);
        }
        p0 = __shfl_sync(0xffffffffu, p0, lane & 16);
        dsum += p0;
        acc = fmaf(p0, f0, acc);
    }
    float invd = 1.f / fmaxf(dsum, 1e-16f);
    float v = acc * invd + bias[t];
    v = v > 0.f ? v : (__expf(v) - 1.f);                 // ELU
    float scale = gamma[t] * rsqrtf(1.0f + 1e-5f);       // eval BN
    out[(size_t)n * F1 + t] = v * scale + beta[t];
}

// ---------------- layer 3: fused GEMM(128->10) + node alphas ----------------
__global__ void gemm10_alpha(const float* __restrict__ A, const float* __restrict__ W,
                             const float* __restrict__ a3s, const float* __restrict__ a3d,
                             float* __restrict__ C, float* __restrict__ als,
                             float* __restrict__ ald) {
    __shared__ float Ws[F1 * NCLS];
    for (int i = threadIdx.x; i < F1 * NCLS; i += blockDim.x) Ws[i] = W[i];
    __syncthreads();
    int warp = (blockIdx.x * blockDim.x + threadIdx.x) >> 5;
    int lane = threadIdx.x & 31;
    if (warp >= NN) return;
    float acc[NCLS];
#pragma unroll
    for (int c = 0; c < NCLS; c++) acc[c] = 0.f;
    const float* arow = A + (size_t)warp * F1;
#pragma unroll
    for (int q = 0; q < 4; q++) {
        int k = lane + q * 32;
        float a = arow[k];
#pragma unroll
        for (int c = 0; c < NCLS; c++) acc[c] += a * Ws[k * NCLS + c];
    }
#pragma unroll
    for (int off = 16; off > 0; off >>= 1)
#pragma unroll
        for (int c = 0; c < NCLS; c++) acc[c] += __shfl_xor_sync(0xffffffffu, acc[c], off);
    if (lane < NCLS) C[(size_t)warp * NCLS + lane] = acc[lane];
    if (lane == 0) {
        float s = 0.f, d = 0.f;
#pragma unroll
        for (int c = 0; c < NCLS; c++) {
            s += acc[c] * __ldg(&a3s[c]);
            d += acc[c] * __ldg(&a3d[c]);
        }
        als[warp] = s;
        ald[warp] = d;
    }
}

// ---------------- layer 3: fused aggregation + bias + log_softmax ------------
__global__ __launch_bounds__(128) void aggregate10_lsm(
    const int* __restrict__ csr, const int* __restrict__ rowptr,
    const int* __restrict__ deg, const float* __restrict__ als,
    const float* __restrict__ ald, const float* __restrict__ hfeat,
    const float* __restrict__ b3, float* __restrict__ out) {
    int warp = (blockIdx.x * blockDim.x + threadIdx.x) >> 5;
    int lane = threadIdx.x & 31;
    if (warp >= NN) return;
    int n = warp;
    int start = rowptr[n];
    int len = deg[n];
    float myald = (lane == 0) ? __ldg(&ald[n]) : 0.f;
    float acc = 0.f, dsum = 0.f;
    int i = 0;
    for (; i + 2 <= len; i += 2) {
        int s0 = __ldg(&csr[start + i]);
        int s1 = __ldg(&csr[start + i + 1]);
        float f0 = (lane < NCLS) ? __ldg(&hfeat[(size_t)s0 * NCLS + lane]) : 0.f;
        float f1 = (lane < NCLS) ? __ldg(&hfeat[(size_t)s1 * NCLS + lane]) : 0.f;
        float p0 = 0.f, p1 = 0.f;
        if (lane == 0) {
            float l0 = __ldg(&als[s0]) + myald;
            float l1 = __ldg(&als[s1]) + myald;
            l0 = l0 > 0.f ? l0 : 0.2f * l0;
            l1 = l1 > 0.f ? l1 : 0.2f * l1;
            p0 = __expf(l0);
            p1 = __expf(l1);
        }
        p0 = __shfl_sync(0xffffffffu, p0, 0);
        p1 = __shfl_sync(0xffffffffu, p1, 0);
        dsum += p0 + p1;
        acc = fmaf(p0, f0, fmaf(p1, f1, acc));
    }
    if (i < len) {
        int s0 = __ldg(&csr[start + i]);
        float f0 = (lane < NCLS) ? __ldg(&hfeat[(size_t)s0 * NCLS + lane]) : 0.f;
        float p0 = 0.f;
        if (lane == 0) {
            float l0 = __ldg(&als[s0]) + myald;
            l0 = l0 > 0.f ? l0 : 0.2f * l0;
            p0 = __expf(l0);
        }
        p0 = __shfl_sync(0xffffffffu, p0, 0);
        dsum += p0;
        acc = fmaf(p0, f0, acc);
    }
    float invd = 1.f / fmaxf(dsum, 1e-16f);
    float val = (lane < NCLS) ? acc * invd + __ldg(&b3[lane]) : -1e30f;
    float m = val;
#pragma unroll
    for (int off = 16; off > 0; off >>= 1)
        m = fmaxf(m, __shfl_xor_sync(0xffffffffu, m, off));
    float ex = (lane < NCLS) ? expf(val - m) : 0.f;
    float ssum = ex;
#pragma unroll
    for (int off = 16; off > 0; off >>= 1)
        ssum += __shfl_xor_sync(0xffffffffu, ssum, off);
    float l = m + logf(ssum);
    if (lane < NCLS) out[(size_t)n * NCLS + lane] = val - l;
}

// ---------------- driver -----------------------------------------------------
extern "C" void kernel_launch(void* const* d_in, const int* in_sizes, int n_in,
                              void* d_out, int out_size) {
    const float* x    = (const float*)d_in[0];
    const int*   ei   = (const int*)d_in[1];
    const float* W1   = (const float*)d_in[2];
    const float* a1s  = (const float*)d_in[3];
    const float* a1d  = (const float*)d_in[4];
    const float* b1   = (const float*)d_in[5];
    const float* g1   = (const float*)d_in[6];
    const float* be1  = (const float*)d_in[7];
    const float* W2   = (const float*)d_in[8];
    const float* a2s  = (const float*)d_in[9];
    const float* a2d  = (const float*)d_in[10];
    const float* b2   = (const float*)d_in[11];
    const float* g2   = (const float*)d_in[12];
    const float* be2  = (const float*)d_in[13];
    const float* W3   = (const float*)d_in[14];
    const float* a3s  = (const float*)d_in[15];
    const float* a3d  = (const float*)d_in[16];
    const float* b3   = (const float*)d_in[17];
    float* out = (float*)d_out;

    float *bufA, *bufB, *als, *ald;
    int *deg, *rowptr, *cursor, *bsum, *boff, *csr;
    cudaGetSymbolAddress((void**)&bufA, g_bufA);
    cudaGetSymbolAddress((void**)&bufB, g_bufB);
    cudaGetSymbolAddress((void**)&als, g_als);
    cudaGetSymbolAddress((void**)&ald, g_ald);
    cudaGetSymbolAddress((void**)&deg, g_deg);
    cudaGetSymbolAddress((void**)&rowptr, g_rowptr);
    cudaGetSymbolAddress((void**)&cursor, g_cursor);
    cudaGetSymbolAddress((void**)&bsum, g_bsum);
    cudaGetSymbolAddress((void**)&boff, g_boff);
    cudaGetSymbolAddress((void**)&csr, g_csr);

    const int TB = 256;
    const int NB_SCAN = cdiv(NN, SCAN_ELEMS);

    // launches 0-4: CSR prep (gemm_tf32 is launch #5 -> ncu -s 5 -c 1 captures it)
    fill_i<<<cdiv(NN, TB), TB>>>(deg, 0, NN);
    hist_dst<<<cdiv(ET, TB), TB>>>(ei, deg);
    scan_s1<<<NB_SCAN, 256>>>(deg, bsum);
    scan_s2<<<1, 256>>>(bsum, boff, NB_SCAN);
    scan_s3<<<NB_SCAN, 256>>>(deg, boff, rowptr, cursor);

    // ---- layer 1 ----
    gemm_tf32<<<cdiv(NN, 128), 256>>>(x, W1, bufA, NN, F_IN);      // launch 5
    csr_scatter<<<cdiv(ET, TB), TB>>>(ei, cursor, csr);
    node_alpha_w<<<cdiv(NN * 32, TB), TB>>>(bufA, a1s, a1d, als, ald);
    aggregate_fused<<<NN, 128>>>(csr, rowptr, deg, als, ald, bufA, b1, g1, be1, bufB);

    // ---- layer 2 ----
    gemm_tf32<<<cdiv(NN, 128), 256>>>(bufB, W2, bufA, NN, F1);
    node_alpha_w<<<cdiv(NN * 32, TB), TB>>>(bufA, a2s, a2d, als, ald);
    aggregate_fused<<<NN, 128>>>(csr, rowptr, deg, als, ald, bufA, b2, g2, be2, bufB);

    // ---- layer 3 ----
    gemm10_alpha<<<cdiv(NN * 32, TB), TB>>>(bufB, W3, a3s, a3d, bufA, als, ald);
    aggregate10_lsm<<<cdiv(NN * 32, 128), 128>>>(csr, rowptr, deg, als, ald, bufA, b3, out);
}

// round 6
// speedup vs baseline: 5.1068x; 1.0755x over previous
#include <cuda_runtime.h>
#include <cuda_bf16.h>
#include <math.h>
#include <stdint.h>

#define NN 100000
#define EE 1600000
#define ET (EE + NN)
#define F_IN 500
#define HID 16
#define HEADS 8
#define F1 (HEADS * HID)   // 128
#define NCLS 10

// ---------------- scratch (static device globals) ---------------------------
__device__ float g_bufA[(size_t)NN * F1];
__device__ float g_bufB[(size_t)NN * F1];
__device__ float g_als[(size_t)NN * HEADS];
__device__ float g_ald[(size_t)NN * HEADS];
__device__ int   g_deg[NN];
__device__ int   g_rowptr[NN];
__device__ int   g_cursor[NN];
__device__ int   g_bsum[256];
__device__ int   g_boff[256];
__device__ int   g_csr[(size_t)ET];          // src node per CSR slot

static inline int cdiv(int a, int b) { return (a + b - 1) / b; }

__device__ __forceinline__ uint32_t smem_u32(const void* p) {
    uint32_t a;
    asm("{ .reg .u64 t; cvta.to.shared.u64 t, %1; cvt.u32.u64 %0, t; }"
        : "=r"(a) : "l"(p));
    return a;
}

// ---------------- tiny utils -------------------------------------------------
__global__ void fill_i(int* p, int v, int n) {
    int i = blockIdx.x * blockDim.x + threadIdx.x;
    if (i < n) p[i] = v;
}

// ---------------- CSR build --------------------------------------------------
__global__ void hist_dst(const int* __restrict__ ei, int* __restrict__ deg) {
    int e = blockIdx.x * blockDim.x + threadIdx.x;
    if (e >= ET) return;
    int dst = (e < EE) ? ei[EE + e] : (e - EE);
    atomicAdd(&deg[dst], 1);
}

#define SCAN_ELEMS 512
__global__ void scan_s1(const int* __restrict__ deg, int* __restrict__ bsum) {
    __shared__ int sm[256];
    int base = blockIdx.x * SCAN_ELEMS;
    int t = threadIdx.x;
    int i0 = base + 2 * t, i1 = base + 2 * t + 1;
    int v = 0;
    if (i0 < NN) v += deg[i0];
    if (i1 < NN) v += deg[i1];
    sm[t] = v;
    __syncthreads();
    for (int off = 128; off > 0; off >>= 1) {
        if (t < off) sm[t] += sm[t + off];
        __syncthreads();
    }
    if (t == 0) bsum[blockIdx.x] = sm[0];
}
__global__ void scan_s2(const int* __restrict__ bsum, int* __restrict__ boff, int nb) {
    __shared__ int sm[256];
    int t = threadIdx.x;
    int v = (t < nb) ? bsum[t] : 0;
    sm[t] = v;
    __syncthreads();
    for (int off = 1; off < 256; off <<= 1) {
        int add = (t >= off) ? sm[t - off] : 0;
        __syncthreads();
        sm[t] += add;
        __syncthreads();
    }
    if (t < nb) boff[t] = sm[t] - v;   // exclusive
}
__global__ void scan_s3(const int* __restrict__ deg, const int* __restrict__ boff,
                        int* __restrict__ rowptr, int* __restrict__ cursor) {
    __shared__ int sm[256];
    int base = blockIdx.x * SCAN_ELEMS;
    int t = threadIdx.x;
    int i0 = base + 2 * t, i1 = base + 2 * t + 1;
    int v0 = (i0 < NN) ? deg[i0] : 0;
    int v1 = (i1 < NN) ? deg[i1] : 0;
    int s = v0 + v1;
    sm[t] = s;
    __syncthreads();
    for (int off = 1; off < 256; off <<= 1) {
        int add = (t >= off) ? sm[t - off] : 0;
        __syncthreads();
        sm[t] += add;
        __syncthreads();
    }
    int ex = sm[t] - s + boff[blockIdx.x];
    if (i0 < NN) { rowptr[i0] = ex;      cursor[i0] = ex; }
    if (i1 < NN) { rowptr[i1] = ex + v0; cursor[i1] = ex + v0; }
}

__global__ void csr_scatter(const int* __restrict__ ei, int* __restrict__ cursor,
                            int* __restrict__ csr) {
    int e = blockIdx.x * blockDim.x + threadIdx.x;
    if (e >= ET) return;
    int src, dst;
    if (e < EE) { src = ei[e]; dst = ei[EE + e]; }
    else        { src = dst = e - EE; }
    int pos = atomicAdd(&cursor[dst], 1);
    csr[pos] = src;
}

// ======== tf32 mma.sync GEMM, cp.async 2-stage pipeline =====================
// C[M,128] = A[M,K] @ B[K,128].  Block tile 256x128, 8 warps (4x2), warp 64x64.
#define TM 256
#define KCH 16
#define ASTR 20                   // floats; conflict-free & 16B-aligned rows
#define BSTR 136
#define ABYTES (TM * ASTR * 4)    // 20480
#define BBYTES (KCH * BSTR * 4)   // 8704
#define STAGEB (ABYTES + BBYTES)  // 29184
#define GSMEM (2 * STAGEB)        // 58368

__global__ __launch_bounds__(256) void gemm_tc(const float* __restrict__ A,
                                               const float* __restrict__ B,
                                               float* __restrict__ C,
                                               int M, int K) {
    extern __shared__ float smf[];
    uint32_t sbase = smem_u32(smf);
    int tid = threadIdx.x, lane = tid & 31, wid = tid >> 5;
    int wm = (wid & 3) * 64, wn = (wid >> 2) * 64;
    int row0 = blockIdx.x * TM;
    int gid = lane >> 2, tk = lane & 3;
    int niter = (K + KCH - 1) / KCH;

    float acc[4][8][4];
#pragma unroll
    for (int mi = 0; mi < 4; mi++)
#pragma unroll
        for (int ni = 0; ni < 8; ni++)
#pragma unroll
            for (int q = 0; q < 4; q++) acc[mi][ni][q] = 0.f;

    auto load_stage = [&](int s, int k0) {
        uint32_t aB = sbase + s * STAGEB;
        uint32_t bB = aB + ABYTES;
#pragma unroll
        for (int i = 0; i < 4; i++) {
            int id = tid + i * 256;          // 1024 chunks: A 256 rows x 4
            int r = id >> 2, c4 = id & 3;
            int gk = k0 + c4 * 4;
            const float* gp = A + (size_t)(row0 + r) * K + gk;
            int remain = K - gk;
            int bytes = 16;
            if (row0 + r >= M || remain <= 0) bytes = 0;
            else if (remain < 4) bytes = remain * 4;
            uint32_t dst = aB + (uint32_t)(r * ASTR + c4 * 4) * 4u;
            asm volatile("cp.async.ca.shared.global [%0], [%1], 16, %2;"
                         :: "r"(dst), "l"(gp), "r"(bytes));
        }
#pragma unroll
        for (int i = 0; i < 2; i++) {
            int id = tid + i * 256;          // 512 chunks: B 16 rows x 32
            int k = id >> 5, c4 = id & 31;
            const float* gp = B + (size_t)(k0 + k) * 128 + c4 * 4;
            int bytes = (k0 + k < K) ? 16 : 0;
            uint32_t dst = bB + (uint32_t)(k * BSTR + c4 * 4) * 4u;
            asm volatile("cp.async.ca.shared.global [%0], [%1], 16, %2;"
                         :: "r"(dst), "l"(gp), "r"(bytes));
        }
        asm volatile("cp.async.commit_group;");
    };

    load_stage(0, 0);

    for (int it = 0; it < niter; it++) {
        if (it + 1 < niter) {
            load_stage((it + 1) & 1, (it + 1) * KCH);
            asm volatile("cp.async.wait_group 1;");
        } else {
            asm volatile("cp.async.wait_group 0;");
        }
        __syncthreads();
        const float* As = smf + ((it & 1) * STAGEB) / 4;
        const float* Bs = As + ABYTES / 4;
#pragma unroll
        for (int ks = 0; ks < 2; ks++) {
            int kb = ks * 8;
            uint32_t af[4][4];
#pragma unroll
            for (int mi = 0; mi < 4; mi++) {
                int r = wm + mi * 16 + gid;
                af[mi][0] = __float_as_uint(As[r * ASTR + kb + tk]);
                af[mi][1] = __float_as_uint(As[(r + 8) * ASTR + kb + tk]);
                af[mi][2] = __float_as_uint(As[r * ASTR + kb + tk + 4]);
                af[mi][3] = __float_as_uint(As[(r + 8) * ASTR + kb + tk + 4]);
            }
            uint32_t bf[8][2];
#pragma unroll
            for (int ni = 0; ni < 8; ni++) {
                int c = wn + ni * 8 + gid;
                bf[ni][0] = __float_as_uint(Bs[(kb + tk) * BSTR + c]);
                bf[ni][1] = __float_as_uint(Bs[(kb + tk + 4) * BSTR + c]);
            }
#pragma unroll
            for (int mi = 0; mi < 4; mi++)
#pragma unroll
                for (int ni = 0; ni < 8; ni++) {
                    asm volatile(
                        "mma.sync.aligned.m16n8k8.row.col.f32.tf32.tf32.f32 "
                        "{%0,%1,%2,%3}, {%4,%5,%6,%7}, {%8,%9}, {%0,%1,%2,%3};"
                        : "+f"(acc[mi][ni][0]), "+f"(acc[mi][ni][1]),
                          "+f"(acc[mi][ni][2]), "+f"(acc[mi][ni][3])
                        : "r"(af[mi][0]), "r"(af[mi][1]), "r"(af[mi][2]), "r"(af[mi][3]),
                          "r"(bf[ni][0]), "r"(bf[ni][1]));
                }
        }
        __syncthreads();
    }

#pragma unroll
    for (int mi = 0; mi < 4; mi++) {
        int r0 = row0 + wm + mi * 16 + gid;
        int r1 = r0 + 8;
#pragma unroll
        for (int ni = 0; ni < 8; ni++) {
            int c = wn + ni * 8 + tk * 2;
            if (r0 < M)
                *(float2*)(C + (size_t)r0 * 128 + c) =
                    make_float2(acc[mi][ni][0], acc[mi][ni][1]);
            if (r1 < M)
                *(float2*)(C + (size_t)r1 * 128 + c) =
                    make_float2(acc[mi][ni][2], acc[mi][ni][3]);
        }
    }
}

// ---------------- node alphas, warp per node (layers 1,2) --------------------
__global__ __launch_bounds__(256) void node_alpha_w(const float* __restrict__ h,
                                                    const float* __restrict__ a_src,
                                                    const float* __restrict__ a_dst,
                                                    float* __restrict__ als,
                                                    float* __restrict__ ald) {
    __shared__ float s_as[F1], s_ad[F1];
    int t = threadIdx.x;
    if (t < F1) { s_as[t] = a_src[t]; s_ad[t] = a_dst[t]; }
    __syncthreads();
    int warp = (blockIdx.x * blockDim.x + t) >> 5;
    int lane = t & 31;
    if (warp >= NN) return;
    int c0 = lane * 4;
    float4 v = *(const float4*)(h + (size_t)warp * F1 + c0);
    float s = v.x * s_as[c0] + v.y * s_as[c0 + 1] + v.z * s_as[c0 + 2] + v.w * s_as[c0 + 3];
    float d = v.x * s_ad[c0] + v.y * s_ad[c0 + 1] + v.z * s_ad[c0 + 2] + v.w * s_ad[c0 + 3];
    s += __shfl_xor_sync(0xffffffffu, s, 1);
    s += __shfl_xor_sync(0xffffffffu, s, 2);
    d += __shfl_xor_sync(0xffffffffu, d, 1);
    d += __shfl_xor_sync(0xffffffffu, d, 2);
    if ((lane & 3) == 0) {
        int hh = lane >> 2;
        als[(size_t)warp * HEADS + hh] = s;
        ald[(size_t)warp * HEADS + hh] = d;
    }
}

// ---------------- fused aggregation (layers 1,2), unroll 4 -------------------
__global__ __launch_bounds__(128) void aggregate_fused(
    const int* __restrict__ csr, const int* __restrict__ rowptr,
    const int* __restrict__ deg, const float* __restrict__ als,
    const float* __restrict__ ald, const float* __restrict__ hfeat,
    const float* __restrict__ bias, const float* __restrict__ gamma,
    const float* __restrict__ beta, float* __restrict__ out) {
    int n = blockIdx.x;
    int t = threadIdx.x;
    int lane = t & 31;
    int start = rowptr[n];
    int len = deg[n];
    int h = t >> 4;
    bool leader = (lane & 15) == 0;
    float myald = leader ? __ldg(&ald[(size_t)n * HEADS + h]) : 0.f;

    float acc = 0.f, dsum = 0.f;
    int i = 0;
    for (; i + 4 <= len; i += 4) {
        int s0 = __ldg(&csr[start + i]);
        int s1 = __ldg(&csr[start + i + 1]);
        int s2 = __ldg(&csr[start + i + 2]);
        int s3 = __ldg(&csr[start + i + 3]);
        float f0 = __ldg(&hfeat[(size_t)s0 * F1 + t]);
        float f1 = __ldg(&hfeat[(size_t)s1 * F1 + t]);
        float f2 = __ldg(&hfeat[(size_t)s2 * F1 + t]);
        float f3 = __ldg(&hfeat[(size_t)s3 * F1 + t]);
        float p0 = 0.f, p1 = 0.f, p2 = 0.f, p3 = 0.f;
        if (leader) {
            float l0 = __ldg(&als[(size_t)s0 * HEADS + h]) + myald;
            float l1 = __ldg(&als[(size_t)s1 * HEADS + h]) + myald;
            float l2 = __ldg(&als[(size_t)s2 * HEADS + h]) + myald;
            float l3 = __ldg(&als[(size_t)s3 * HEADS + h]) + myald;
            l0 = l0 > 0.f ? l0 : 0.2f * l0;
            l1 = l1 > 0.f ? l1 : 0.2f * l1;
            l2 = l2 > 0.f ? l2 : 0.2f * l2;
            l3 = l3 > 0.f ? l3 : 0.2f * l3;
            p0 = __expf(l0); p1 = __expf(l1); p2 = __expf(l2); p3 = __expf(l3);
        }
        p0 = __shfl_sync(0xffffffffu, p0, lane & 16);
        p1 = __shfl_sync(0xffffffffu, p1, lane & 16);
        p2 = __shfl_sync(0xffffffffu, p2, lane & 16);
        p3 = __shfl_sync(0xffffffffu, p3, lane & 16);
        dsum += (p0 + p1) + (p2 + p3);
        acc = fmaf(p0, f0, acc);
        acc = fmaf(p1, f1, acc);
        acc = fmaf(p2, f2, acc);
        acc = fmaf(p3, f3, acc);
    }
    for (; i < len; i++) {
        int s0 = __ldg(&csr[start + i]);
        float f0 = __ldg(&hfeat[(size_t)s0 * F1 + t]);
        float p0 = 0.f;
        if (leader) {
            float l0 = __ldg(&als[(size_t)s0 * HEADS + h]) + myald;
            l0 = l0 > 0.f ? l0 : 0.2f * l0;
            p0 = __expf(l0);
        }
        p0 = __shfl_sync(0xffffffffu, p0, lane & 16);
        dsum += p0;
        acc = fmaf(p0, f0, acc);
    }
    float invd = 1.f / fmaxf(dsum, 1e-16f);
    float v = acc * invd + bias[t];
    v = v > 0.f ? v : (__expf(v) - 1.f);                 // ELU
    float scale = gamma[t] * rsqrtf(1.0f + 1e-5f);       // eval BN
    out[(size_t)n * F1 + t] = v * scale + beta[t];
}

// ---------------- layer 3: fused GEMM(128->10) + node alphas ----------------
__global__ void gemm10_alpha(const float* __restrict__ A, const float* __restrict__ W,
                             const float* __restrict__ a3s, const float* __restrict__ a3d,
                             float* __restrict__ C, float* __restrict__ als,
                             float* __restrict__ ald) {
    __shared__ float Ws[F1 * NCLS];
    for (int i = threadIdx.x; i < F1 * NCLS; i += blockDim.x) Ws[i] = W[i];
    __syncthreads();
    int warp = (blockIdx.x * blockDim.x + threadIdx.x) >> 5;
    int lane = threadIdx.x & 31;
    if (warp >= NN) return;
    float acc[NCLS];
#pragma unroll
    for (int c = 0; c < NCLS; c++) acc[c] = 0.f;
    const float* arow = A + (size_t)warp * F1;
#pragma unroll
    for (int q = 0; q < 4; q++) {
        int k = lane + q * 32;
        float a = arow[k];
#pragma unroll
        for (int c = 0; c < NCLS; c++) acc[c] += a * Ws[k * NCLS + c];
    }
#pragma unroll
    for (int off = 16; off > 0; off >>= 1)
#pragma unroll
        for (int c = 0; c < NCLS; c++) acc[c] += __shfl_xor_sync(0xffffffffu, acc[c], off);
    if (lane < NCLS) C[(size_t)warp * NCLS + lane] = acc[lane];
    if (lane == 0) {
        float s = 0.f, d = 0.f;
#pragma unroll
        for (int c = 0; c < NCLS; c++) {
            s += acc[c] * __ldg(&a3s[c]);
            d += acc[c] * __ldg(&a3d[c]);
        }
        als[warp] = s;
        ald[warp] = d;
    }
}

// ---------------- layer 3: fused aggregation + bias + log_softmax ------------
__global__ __launch_bounds__(128) void aggregate10_lsm(
    const int* __restrict__ csr, const int* __restrict__ rowptr,
    const int* __restrict__ deg, const float* __restrict__ als,
    const float* __restrict__ ald, const float* __restrict__ hfeat,
    const float* __restrict__ b3, float* __restrict__ out) {
    int warp = (blockIdx.x * blockDim.x + threadIdx.x) >> 5;
    int lane = threadIdx.x & 31;
    if (warp >= NN) return;
    int n = warp;
    int start = rowptr[n];
    int len = deg[n];
    float myald = (lane == 0) ? __ldg(&ald[n]) : 0.f;
    float acc = 0.f, dsum = 0.f;
    int i = 0;
    for (; i + 2 <= len; i += 2) {
        int s0 = __ldg(&csr[start + i]);
        int s1 = __ldg(&csr[start + i + 1]);
        float f0 = (lane < NCLS) ? __ldg(&hfeat[(size_t)s0 * NCLS + lane]) : 0.f;
        float f1 = (lane < NCLS) ? __ldg(&hfeat[(size_t)s1 * NCLS + lane]) : 0.f;
        float p0 = 0.f, p1 = 0.f;
        if (lane == 0) {
            float l0 = __ldg(&als[s0]) + myald;
            float l1 = __ldg(&als[s1]) + myald;
            l0 = l0 > 0.f ? l0 : 0.2f * l0;
            l1 = l1 > 0.f ? l1 : 0.2f * l1;
            p0 = __expf(l0);
            p1 = __expf(l1);
        }
        p0 = __shfl_sync(0xffffffffu, p0, 0);
        p1 = __shfl_sync(0xffffffffu, p1, 0);
        dsum += p0 + p1;
        acc = fmaf(p0, f0, fmaf(p1, f1, acc));
    }
    if (i < len) {
        int s0 = __ldg(&csr[start + i]);
        float f0 = (lane < NCLS) ? __ldg(&hfeat[(size_t)s0 * NCLS + lane]) : 0.f;
        float p0 = 0.f;
        if (lane == 0) {
            float l0 = __ldg(&als[s0]) + myald;
            l0 = l0 > 0.f ? l0 : 0.2f * l0;
            p0 = __expf(l0);
        }
        p0 = __shfl_sync(0xffffffffu, p0, 0);
        dsum += p0;
        acc = fmaf(p0, f0, acc);
    }
    float invd = 1.f / fmaxf(dsum, 1e-16f);
    float val = (lane < NCLS) ? acc * invd + __ldg(&b3[lane]) : -1e30f;
    float m = val;
#pragma unroll
    for (int off = 16; off > 0; off >>= 1)
        m = fmaxf(m, __shfl_xor_sync(0xffffffffu, m, off));
    float ex = (lane < NCLS) ? expf(val - m) : 0.f;
    float ssum = ex;
#pragma unroll
    for (int off = 16; off > 0; off >>= 1)
        ssum += __shfl_xor_sync(0xffffffffu, ssum, off);
    float l = m + logf(ssum);
    if (lane < NCLS) out[(size_t)n * NCLS + lane] = val - l;
}

// ---------------- driver -----------------------------------------------------
extern "C" void kernel_launch(void* const* d_in, const int* in_sizes, int n_in,
                              void* d_out, int out_size) {
    const float* x    = (const float*)d_in[0];
    const int*   ei   = (const int*)d_in[1];
    const float* W1   = (const float*)d_in[2];
    const float* a1s  = (const float*)d_in[3];
    const float* a1d  = (const float*)d_in[4];
    const float* b1   = (const float*)d_in[5];
    const float* g1   = (const float*)d_in[6];
    const float* be1  = (const float*)d_in[7];
    const float* W2   = (const float*)d_in[8];
    const float* a2s  = (const float*)d_in[9];
    const float* a2d  = (const float*)d_in[10];
    const float* b2   = (const float*)d_in[11];
    const float* g2   = (const float*)d_in[12];
    const float* be2  = (const float*)d_in[13];
    const float* W3   = (const float*)d_in[14];
    const float* a3s  = (const float*)d_in[15];
    const float* a3d  = (const float*)d_in[16];
    const float* b3   = (const float*)d_in[17];
    float* out = (float*)d_out;

    float *bufA, *bufB, *als, *ald;
    int *deg, *rowptr, *cursor, *bsum, *boff, *csr;
    cudaGetSymbolAddress((void**)&bufA, g_bufA);
    cudaGetSymbolAddress((void**)&bufB, g_bufB);
    cudaGetSymbolAddress((void**)&als, g_als);
    cudaGetSymbolAddress((void**)&ald, g_ald);
    cudaGetSymbolAddress((void**)&deg, g_deg);
    cudaGetSymbolAddress((void**)&rowptr, g_rowptr);
    cudaGetSymbolAddress((void**)&cursor, g_cursor);
    cudaGetSymbolAddress((void**)&bsum, g_bsum);
    cudaGetSymbolAddress((void**)&boff, g_boff);
    cudaGetSymbolAddress((void**)&csr, g_csr);

    cudaFuncSetAttribute(gemm_tc, cudaFuncAttributeMaxDynamicSharedMemorySize, GSMEM);

    const int TB = 256;
    const int NB_SCAN = cdiv(NN, SCAN_ELEMS);
    const int NGRID = cdiv(NN, TM);

    // launches 0-2: CSR prep; launch 3 = gemm_tc (ncu capture lands on idx 3)
    fill_i<<<cdiv(NN, TB), TB>>>(deg, 0, NN);
    hist_dst<<<cdiv(ET, TB), TB>>>(ei, deg);
    scan_s1<<<NB_SCAN, 256>>>(deg, bsum);

    gemm_tc<<<NGRID, 256, GSMEM>>>(x, W1, bufA, NN, F_IN);          // layer 1 GEMM

    scan_s2<<<1, 256>>>(bsum, boff, NB_SCAN);
    scan_s3<<<NB_SCAN, 256>>>(deg, boff, rowptr, cursor);
    csr_scatter<<<cdiv(ET, TB), TB>>>(ei, cursor, csr);

    // ---- layer 1 rest ----
    node_alpha_w<<<cdiv(NN * 32, TB), TB>>>(bufA, a1s, a1d, als, ald);
    aggregate_fused<<<NN, 128>>>(csr, rowptr, deg, als, ald, bufA, b1, g1, be1, bufB);

    // ---- layer 2 ----
    gemm_tc<<<NGRID, 256, GSMEM>>>(bufB, W2, bufA, NN, F1);
    node_alpha_w<<<cdiv(NN * 32, TB), TB>>>(bufA, a2s, a2d, als, ald);
    aggregate_fused<<<NN, 128>>>(csr, rowptr, deg, als, ald, bufA, b2, g2, be2, bufB);

    // ---- layer 3 ----
    gemm10_alpha<<<cdiv(NN * 32, TB), TB>>>(bufB, W3, a3s, a3d, bufA, als, ald);
    aggregate10_lsm<<<cdiv(NN * 32, 128), 128>>>(csr, rowptr, deg, als, ald, bufA, b3, out);
}

// round 7
// speedup vs baseline: 7.1208x; 1.3944x over previous
#include <cuda_runtime.h>
#include <cuda_fp16.h>
#include <math.h>
#include <stdint.h>

#define NN 100000
#define EE 1600000
#define ET (EE + NN)
#define F_IN 500
#define HID 16
#define HEADS 8
#define F1 (HEADS * HID)   // 128
#define NCLS 10

// ---------------- scratch (static device globals) ---------------------------
__device__ __half g_bufH[(size_t)NN * F1];   // fp16 features (gemm output)
__device__ float  g_bufA[(size_t)NN * F1];   // fp32 (layer-3 gemm out reuses)
__device__ float  g_bufB[(size_t)NN * F1];   // fp32 aggregate output
__device__ float  g_als[(size_t)NN * HEADS];
__device__ float  g_ald[(size_t)NN * HEADS];
__device__ int    g_deg[NN];
__device__ int    g_rowptr[NN];
__device__ int    g_cursor[NN];
__device__ int    g_bsum[256];
__device__ int    g_boff[256];
__device__ int    g_csr[(size_t)ET];         // src node per CSR slot

static inline int cdiv(int a, int b) { return (a + b - 1) / b; }

__device__ __forceinline__ uint32_t smem_u32(const void* p) {
    uint32_t a;
    asm("{ .reg .u64 t; cvta.to.shared.u64 t, %1; cvt.u32.u64 %0, t; }"
        : "=r"(a) : "l"(p));
    return a;
}
__device__ __forceinline__ uint32_t rna(float v) {
    uint32_t t;
    asm("cvt.rna.tf32.f32 %0, %1;" : "=r"(t) : "f"(v));
    return t;
}

// ---------------- tiny utils -------------------------------------------------
__global__ void fill_i(int* p, int v, int n) {
    int i = blockIdx.x * blockDim.x + threadIdx.x;
    if (i < n) p[i] = v;
}

// ---------------- CSR build --------------------------------------------------
__global__ void hist_dst(const int* __restrict__ ei, int* __restrict__ deg) {
    int e = blockIdx.x * blockDim.x + threadIdx.x;
    if (e >= ET) return;
    int dst = (e < EE) ? ei[EE + e] : (e - EE);
    atomicAdd(&deg[dst], 1);
}

#define SCAN_ELEMS 512
__global__ void scan_s1(const int* __restrict__ deg, int* __restrict__ bsum) {
    __shared__ int sm[256];
    int base = blockIdx.x * SCAN_ELEMS;
    int t = threadIdx.x;
    int i0 = base + 2 * t, i1 = base + 2 * t + 1;
    int v = 0;
    if (i0 < NN) v += deg[i0];
    if (i1 < NN) v += deg[i1];
    sm[t] = v;
    __syncthreads();
    for (int off = 128; off > 0; off >>= 1) {
        if (t < off) sm[t] += sm[t + off];
        __syncthreads();
    }
    if (t == 0) bsum[blockIdx.x] = sm[0];
}
__global__ void scan_s2(const int* __restrict__ bsum, int* __restrict__ boff, int nb) {
    __shared__ int sm[256];
    int t = threadIdx.x;
    int v = (t < nb) ? bsum[t] : 0;
    sm[t] = v;
    __syncthreads();
    for (int off = 1; off < 256; off <<= 1) {
        int add = (t >= off) ? sm[t - off] : 0;
        __syncthreads();
        sm[t] += add;
        __syncthreads();
    }
    if (t < nb) boff[t] = sm[t] - v;   // exclusive
}
__global__ void scan_s3(const int* __restrict__ deg, const int* __restrict__ boff,
                        int* __restrict__ rowptr, int* __restrict__ cursor) {
    __shared__ int sm[256];
    int base = blockIdx.x * SCAN_ELEMS;
    int t = threadIdx.x;
    int i0 = base + 2 * t, i1 = base + 2 * t + 1;
    int v0 = (i0 < NN) ? deg[i0] : 0;
    int v1 = (i1 < NN) ? deg[i1] : 0;
    int s = v0 + v1;
    sm[t] = s;
    __syncthreads();
    for (int off = 1; off < 256; off <<= 1) {
        int add = (t >= off) ? sm[t - off] : 0;
        __syncthreads();
        sm[t] += add;
        __syncthreads();
    }
    int ex = sm[t] - s + boff[blockIdx.x];
    if (i0 < NN) { rowptr[i0] = ex;      cursor[i0] = ex; }
    if (i1 < NN) { rowptr[i1] = ex + v0; cursor[i1] = ex + v0; }
}

__global__ void csr_scatter(const int* __restrict__ ei, int* __restrict__ cursor,
                            int* __restrict__ csr) {
    int e = blockIdx.x * blockDim.x + threadIdx.x;
    if (e >= ET) return;
    int src, dst;
    if (e < EE) { src = ei[e]; dst = ei[EE + e]; }
    else        { src = dst = e - EE; }
    int pos = atomicAdd(&cursor[dst], 1);
    csr[pos] = src;
}

// ======== tf32 mma.sync GEMM, cp.async 2-stage, fp16 output ================
// C[M,128] = A[M,K] @ B[K,128]. Block 256x128, 8 warps (4x2), warp 64x64.
#define TM 256
#define KCH 16
#define ASTR 20
#define BSTR 136
#define ABYTES (TM * ASTR * 4)
#define BBYTES (KCH * BSTR * 4)
#define STAGEB (ABYTES + BBYTES)
#define GSMEM (2 * STAGEB)

__global__ __launch_bounds__(256) void gemm_tc(const float* __restrict__ A,
                                               const float* __restrict__ B,
                                               __half* __restrict__ H,
                                               int M, int K) {
    extern __shared__ float smf[];
    uint32_t sbase = smem_u32(smf);
    int tid = threadIdx.x, lane = tid & 31, wid = tid >> 5;
    int wm = (wid & 3) * 64, wn = (wid >> 2) * 64;
    int row0 = blockIdx.x * TM;
    int gid = lane >> 2, tk = lane & 3;
    int niter = (K + KCH - 1) / KCH;

    float acc[4][8][4];
#pragma unroll
    for (int mi = 0; mi < 4; mi++)
#pragma unroll
        for (int ni = 0; ni < 8; ni++)
#pragma unroll
            for (int q = 0; q < 4; q++) acc[mi][ni][q] = 0.f;

    auto load_stage = [&](int s, int k0) {
        uint32_t aB = sbase + s * STAGEB;
        uint32_t bB = aB + ABYTES;
#pragma unroll
        for (int i = 0; i < 4; i++) {
            int id = tid + i * 256;
            int r = id >> 2, c4 = id & 3;
            int gk = k0 + c4 * 4;
            const float* gp = A + (size_t)(row0 + r) * K + gk;
            int remain = K - gk;
            int bytes = 16;
            if (row0 + r >= M || remain <= 0) bytes = 0;
            else if (remain < 4) bytes = remain * 4;
            uint32_t dst = aB + (uint32_t)(r * ASTR + c4 * 4) * 4u;
            asm volatile("cp.async.ca.shared.global [%0], [%1], 16, %2;"
                         :: "r"(dst), "l"(gp), "r"(bytes));
        }
#pragma unroll
        for (int i = 0; i < 2; i++) {
            int id = tid + i * 256;
            int k = id >> 5, c4 = id & 31;
            const float* gp = B + (size_t)(k0 + k) * 128 + c4 * 4;
            int bytes = (k0 + k < K) ? 16 : 0;
            uint32_t dst = bB + (uint32_t)(k * BSTR + c4 * 4) * 4u;
            asm volatile("cp.async.ca.shared.global [%0], [%1], 16, %2;"
                         :: "r"(dst), "l"(gp), "r"(bytes));
        }
        asm volatile("cp.async.commit_group;");
    };

    load_stage(0, 0);

    for (int it = 0; it < niter; it++) {
        if (it + 1 < niter) {
            load_stage((it + 1) & 1, (it + 1) * KCH);
            asm volatile("cp.async.wait_group 1;");
        } else {
            asm volatile("cp.async.wait_group 0;");
        }
        __syncthreads();
        const float* As = smf + ((it & 1) * STAGEB) / 4;
        const float* Bs = As + ABYTES / 4;
#pragma unroll
        for (int ks = 0; ks < 2; ks++) {
            int kb = ks * 8;
            uint32_t af[4][4];
#pragma unroll
            for (int mi = 0; mi < 4; mi++) {
                int r = wm + mi * 16 + gid;
                af[mi][0] = rna(As[r * ASTR + kb + tk]);
                af[mi][1] = rna(As[(r + 8) * ASTR + kb + tk]);
                af[mi][2] = rna(As[r * ASTR + kb + tk + 4]);
                af[mi][3] = rna(As[(r + 8) * ASTR + kb + tk + 4]);
            }
            uint32_t bf[8][2];
#pragma unroll
            for (int ni = 0; ni < 8; ni++) {
                int c = wn + ni * 8 + gid;
                bf[ni][0] = rna(Bs[(kb + tk) * BSTR + c]);
                bf[ni][1] = rna(Bs[(kb + tk + 4) * BSTR + c]);
            }
#pragma unroll
            for (int mi = 0; mi < 4; mi++)
#pragma unroll
                for (int ni = 0; ni < 8; ni++) {
                    asm volatile(
                        "mma.sync.aligned.m16n8k8.row.col.f32.tf32.tf32.f32 "
                        "{%0,%1,%2,%3}, {%4,%5,%6,%7}, {%8,%9}, {%0,%1,%2,%3};"
                        : "+f"(acc[mi][ni][0]), "+f"(acc[mi][ni][1]),
                          "+f"(acc[mi][ni][2]), "+f"(acc[mi][ni][3])
                        : "r"(af[mi][0]), "r"(af[mi][1]), "r"(af[mi][2]), "r"(af[mi][3]),
                          "r"(bf[ni][0]), "r"(bf[ni][1]));
                }
        }
        __syncthreads();
    }

#pragma unroll
    for (int mi = 0; mi < 4; mi++) {
        int r0 = row0 + wm + mi * 16 + gid;
        int r1 = r0 + 8;
#pragma unroll
        for (int ni = 0; ni < 8; ni++) {
            int c = wn + ni * 8 + tk * 2;
            if (r0 < M)
                *(__half2*)(H + (size_t)r0 * 128 + c) =
                    __floats2half2_rn(acc[mi][ni][0], acc[mi][ni][1]);
            if (r1 < M)
                *(__half2*)(H + (size_t)r1 * 128 + c) =
                    __floats2half2_rn(acc[mi][ni][2], acc[mi][ni][3]);
        }
    }
}

// ---------------- node alphas from fp16 features, warp per node --------------
__global__ __launch_bounds__(256) void node_alpha_w(const __half* __restrict__ h,
                                                    const float* __restrict__ a_src,
                                                    const float* __restrict__ a_dst,
                                                    float* __restrict__ als,
                                                    float* __restrict__ ald) {
    __shared__ float s_as[F1], s_ad[F1];
    int t = threadIdx.x;
    if (t < F1) { s_as[t] = a_src[t]; s_ad[t] = a_dst[t]; }
    __syncthreads();
    int warp = (blockIdx.x * blockDim.x + t) >> 5;
    int lane = t & 31;
    if (warp >= NN) return;
    int c0 = lane * 4;
    const __half2* hp = (const __half2*)(h + (size_t)warp * F1) + lane * 2;
    float2 v0 = __half22float2(hp[0]);
    float2 v1 = __half22float2(hp[1]);
    float s = v0.x * s_as[c0] + v0.y * s_as[c0 + 1] + v1.x * s_as[c0 + 2] + v1.y * s_as[c0 + 3];
    float d = v0.x * s_ad[c0] + v0.y * s_ad[c0 + 1] + v1.x * s_ad[c0 + 2] + v1.y * s_ad[c0 + 3];
    s += __shfl_xor_sync(0xffffffffu, s, 1);
    s += __shfl_xor_sync(0xffffffffu, s, 2);
    d += __shfl_xor_sync(0xffffffffu, d, 1);
    d += __shfl_xor_sync(0xffffffffu, d, 2);
    if ((lane & 3) == 0) {
        int hh = lane >> 2;
        als[(size_t)warp * HEADS + hh] = s;
        ald[(size_t)warp * HEADS + hh] = d;
    }
}

// ---------------- fused aggregation v2 (layers 1,2) --------------------------
// 128 threads = 4 warps; each warp gathers whole fp16 rows (256B), strided edges.
__global__ __launch_bounds__(128) void aggregate_fused(
    const int* __restrict__ csr, const int* __restrict__ rowptr,
    const int* __restrict__ deg, const float* __restrict__ als,
    const float* __restrict__ ald, const __half* __restrict__ hfeat,
    const float* __restrict__ bias, const float* __restrict__ gamma,
    const float* __restrict__ beta, float* __restrict__ out) {
    __shared__ float4 s_acc[3][32];
    __shared__ float  s_d[4][8];
    int n = blockIdx.x;
    int t = threadIdx.x;
    int w = t >> 5, l = t & 31;
    int h = l >> 2;               // head for my 4 cols
    int c0 = l * 4;
    int start = rowptr[n];
    int len = deg[n];
    float myald = __ldg(&ald[(size_t)n * HEADS + h]);

    float4 acc = make_float4(0.f, 0.f, 0.f, 0.f);
    float dsum = 0.f;

    auto edge = [&](int s) {
        const __half2* hp = (const __half2*)(hfeat + (size_t)s * F1) + l * 2;
        __half2 q0 = __ldg(hp);
        __half2 q1 = __ldg(hp + 1);
        float al = __ldg(&als[(size_t)s * HEADS + h]) + myald;
        al = al > 0.f ? al : 0.2f * al;
        float p = __expf(al);
        dsum += p;
        float2 f0 = __half22float2(q0);
        float2 f1 = __half22float2(q1);
        acc.x = fmaf(p, f0.x, acc.x);
        acc.y = fmaf(p, f0.y, acc.y);
        acc.z = fmaf(p, f1.x, acc.z);
        acc.w = fmaf(p, f1.y, acc.w);
    };

    int i = w;
    for (; i + 4 < len; i += 8) {
        int s0 = __ldg(&csr[start + i]);
        int s1 = __ldg(&csr[start + i + 4]);
        edge(s0);
        edge(s1);
    }
    if (i < len) {
        int s0 = __ldg(&csr[start + i]);
        edge(s0);
    }

    if (w > 0) s_acc[w - 1][l] = acc;
    if ((l & 3) == 0) s_d[w][h] = dsum;
    __syncthreads();
    if (w == 0) {
        float4 a1 = s_acc[0][l], a2 = s_acc[1][l], a3 = s_acc[2][l];
        acc.x += a1.x + a2.x + a3.x;
        acc.y += a1.y + a2.y + a3.y;
        acc.z += a1.z + a2.z + a3.z;
        acc.w += a1.w + a2.w + a3.w;
        float dall = s_d[0][h] + s_d[1][h] + s_d[2][h] + s_d[3][h];
        float invd = 1.f / fmaxf(dall, 1e-16f);
        float4 bb = *(const float4*)(bias + c0);
        float4 gg = *(const float4*)(gamma + c0);
        float4 be = *(const float4*)(beta + c0);
        float bnf = rsqrtf(1.0f + 1e-5f);
        float v0 = acc.x * invd + bb.x;
        float v1 = acc.y * invd + bb.y;
        float v2 = acc.z * invd + bb.z;
        float v3 = acc.w * invd + bb.w;
        v0 = v0 > 0.f ? v0 : (__expf(v0) - 1.f);
        v1 = v1 > 0.f ? v1 : (__expf(v1) - 1.f);
        v2 = v2 > 0.f ? v2 : (__expf(v2) - 1.f);
        v3 = v3 > 0.f ? v3 : (__expf(v3) - 1.f);
        float4 r;
        r.x = v0 * gg.x * bnf + be.x;
        r.y = v1 * gg.y * bnf + be.y;
        r.z = v2 * gg.z * bnf + be.z;
        r.w = v3 * gg.w * bnf + be.w;
        *(float4*)(out + (size_t)n * F1 + c0) = r;
    }
}

// ---------------- layer 3: fused GEMM(128->10) + node alphas ----------------
__global__ void gemm10_alpha(const float* __restrict__ A, const float* __restrict__ W,
                             const float* __restrict__ a3s, const float* __restrict__ a3d,
                             float* __restrict__ C, float* __restrict__ als,
                             float* __restrict__ ald) {
    __shared__ float Ws[F1 * NCLS];
    for (int i = threadIdx.x; i < F1 * NCLS; i += blockDim.x) Ws[i] = W[i];
    __syncthreads();
    int warp = (blockIdx.x * blockDim.x + threadIdx.x) >> 5;
    int lane = threadIdx.x & 31;
    if (warp >= NN) return;
    float acc[NCLS];
#pragma unroll
    for (int c = 0; c < NCLS; c++) acc[c] = 0.f;
    const float* arow = A + (size_t)warp * F1;
#pragma unroll
    for (int q = 0; q < 4; q++) {
        int k = lane + q * 32;
        float a = arow[k];
#pragma unroll
        for (int c = 0; c < NCLS; c++) acc[c] += a * Ws[k * NCLS + c];
    }
#pragma unroll
    for (int off = 16; off > 0; off >>= 1)
#pragma unroll
        for (int c = 0; c < NCLS; c++) acc[c] += __shfl_xor_sync(0xffffffffu, acc[c], off);
    if (lane < NCLS) C[(size_t)warp * NCLS + lane] = acc[lane];
    if (lane == 0) {
        float s = 0.f, d = 0.f;
#pragma unroll
        for (int c = 0; c < NCLS; c++) {
            s += acc[c] * __ldg(&a3s[c]);
            d += acc[c] * __ldg(&a3d[c]);
        }
        als[warp] = s;
        ald[warp] = d;
    }
}

// ---------------- layer 3: fused aggregation + bias + log_softmax ------------
__global__ __launch_bounds__(128) void aggregate10_lsm(
    const int* __restrict__ csr, const int* __restrict__ rowptr,
    const int* __restrict__ deg, const float* __restrict__ als,
    const float* __restrict__ ald, const float* __restrict__ hfeat,
    const float* __restrict__ b3, float* __restrict__ out) {
    int warp = (blockIdx.x * blockDim.x + threadIdx.x) >> 5;
    int lane = threadIdx.x & 31;
    if (warp >= NN) return;
    int n = warp;
    int start = rowptr[n];
    int len = deg[n];
    float myald = (lane == 0) ? __ldg(&ald[n]) : 0.f;
    float acc = 0.f, dsum = 0.f;
    int i = 0;
    for (; i + 2 <= len; i += 2) {
        int s0 = __ldg(&csr[start + i]);
        int s1 = __ldg(&csr[start + i + 1]);
        float f0 = (lane < NCLS) ? __ldg(&hfeat[(size_t)s0 * NCLS + lane]) : 0.f;
        float f1 = (lane < NCLS) ? __ldg(&hfeat[(size_t)s1 * NCLS + lane]) : 0.f;
        float p0 = 0.f, p1 = 0.f;
        if (lane == 0) {
            float l0 = __ldg(&als[s0]) + myald;
            float l1 = __ldg(&als[s1]) + myald;
            l0 = l0 > 0.f ? l0 : 0.2f * l0;
            l1 = l1 > 0.f ? l1 : 0.2f * l1;
            p0 = __expf(l0);
            p1 = __expf(l1);
        }
        p0 = __shfl_sync(0xffffffffu, p0, 0);
        p1 = __shfl_sync(0xffffffffu, p1, 0);
        dsum += p0 + p1;
        acc = fmaf(p0, f0, fmaf(p1, f1, acc));
    }
    if (i < len) {
        int s0 = __ldg(&csr[start + i]);
        float f0 = (lane < NCLS) ? __ldg(&hfeat[(size_t)s0 * NCLS + lane]) : 0.f;
        float p0 = 0.f;
        if (lane == 0) {
            float l0 = __ldg(&als[s0]) + myald;
            l0 = l0 > 0.f ? l0 : 0.2f * l0;
            p0 = __expf(l0);
        }
        p0 = __shfl_sync(0xffffffffu, p0, 0);
        dsum += p0;
        acc = fmaf(p0, f0, acc);
    }
    float invd = 1.f / fmaxf(dsum, 1e-16f);
    float val = (lane < NCLS) ? acc * invd + __ldg(&b3[lane]) : -1e30f;
    float m = val;
#pragma unroll
    for (int off = 16; off > 0; off >>= 1)
        m = fmaxf(m, __shfl_xor_sync(0xffffffffu, m, off));
    float ex = (lane < NCLS) ? expf(val - m) : 0.f;
    float ssum = ex;
#pragma unroll
    for (int off = 16; off > 0; off >>= 1)
        ssum += __shfl_xor_sync(0xffffffffu, ssum, off);
    float l = m + logf(ssum);
    if (lane < NCLS) out[(size_t)n * NCLS + lane] = val - l;
}

// ---------------- driver -----------------------------------------------------
extern "C" void kernel_launch(void* const* d_in, const int* in_sizes, int n_in,
                              void* d_out, int out_size) {
    const float* x    = (const float*)d_in[0];
    const int*   ei   = (const int*)d_in[1];
    const float* W1   = (const float*)d_in[2];
    const float* a1s  = (const float*)d_in[3];
    const float* a1d  = (const float*)d_in[4];
    const float* b1   = (const float*)d_in[5];
    const float* g1   = (const float*)d_in[6];
    const float* be1  = (const float*)d_in[7];
    const float* W2   = (const float*)d_in[8];
    const float* a2s  = (const float*)d_in[9];
    const float* a2d  = (const float*)d_in[10];
    const float* b2   = (const float*)d_in[11];
    const float* g2   = (const float*)d_in[12];
    const float* be2  = (const float*)d_in[13];
    const float* W3   = (const float*)d_in[14];
    const float* a3s  = (const float*)d_in[15];
    const float* a3d  = (const float*)d_in[16];
    const float* b3   = (const float*)d_in[17];
    float* out = (float*)d_out;

    __half* bufH;
    float *bufA, *bufB, *als, *ald;
    int *deg, *rowptr, *cursor, *bsum, *boff, *csr;
    cudaGetSymbolAddress((void**)&bufH, g_bufH);
    cudaGetSymbolAddress((void**)&bufA, g_bufA);
    cudaGetSymbolAddress((void**)&bufB, g_bufB);
    cudaGetSymbolAddress((void**)&als, g_als);
    cudaGetSymbolAddress((void**)&ald, g_ald);
    cudaGetSymbolAddress((void**)&deg, g_deg);
    cudaGetSymbolAddress((void**)&rowptr, g_rowptr);
    cudaGetSymbolAddress((void**)&cursor, g_cursor);
    cudaGetSymbolAddress((void**)&bsum, g_bsum);
    cudaGetSymbolAddress((void**)&boff, g_boff);
    cudaGetSymbolAddress((void**)&csr, g_csr);

    cudaFuncSetAttribute(gemm_tc, cudaFuncAttributeMaxDynamicSharedMemorySize, GSMEM);

    const int TB = 256;
    const int NB_SCAN = cdiv(NN, SCAN_ELEMS);
    const int NGRID = cdiv(NN, TM);

    // launches 0-2: CSR prep; launch 3 = gemm_tc (ncu capture idx 3)
    fill_i<<<cdiv(NN, TB), TB>>>(deg, 0, NN);
    hist_dst<<<cdiv(ET, TB), TB>>>(ei, deg);
    scan_s1<<<NB_SCAN, 256>>>(deg, bsum);

    gemm_tc<<<NGRID, 256, GSMEM>>>(x, W1, bufH, NN, F_IN);          // layer 1 GEMM

    scan_s2<<<1, 256>>>(bsum, boff, NB_SCAN);
    scan_s3<<<NB_SCAN, 256>>>(deg, boff, rowptr, cursor);
    csr_scatter<<<cdiv(ET, TB), TB>>>(ei, cursor, csr);

    // ---- layer 1 rest ----
    node_alpha_w<<<cdiv(NN * 32, TB), TB>>>(bufH, a1s, a1d, als, ald);
    aggregate_fused<<<NN, 128>>>(csr, rowptr, deg, als, ald, bufH, b1, g1, be1, bufB);

    // ---- layer 2 ----
    gemm_tc<<<NGRID, 256, GSMEM>>>(bufB, W2, bufH, NN, F1);
    node_alpha_w<<<cdiv(NN * 32, TB), TB>>>(bufH, a2s, a2d, als, ald);
    aggregate_fused<<<NN, 128>>>(csr, rowptr, deg, als, ald, bufH, b2, g2, be2, bufB);

    // ---- layer 3 ----
    gemm10_alpha<<<cdiv(NN * 32, TB), TB>>>(bufB, W3, a3s, a3d, bufA, als, ald);
    aggregate10_lsm<<<cdiv(NN * 32, 128), 128>>>(csr, rowptr, deg, als, ald, bufA, b3, out);
}